// round 1
// baseline (speedup 1.0000x reference)
#include <cuda_runtime.h>
#include <math.h>

#define KARY 4
#define LEVELS 9
#define N_NODES 87381          // (4^9-1)/3
#define LEAF_START 21845       // starts[8]
#define LEAF_N 65536

// ---------------- scratch (device globals: allocation-free rule) ----------------
__device__ float g_xiouf[(size_t)N_NODES * 1024];   // [iou(768) | f(256)] per node
__device__ float g_kv[(size_t)65536 * 512];         // [k(256) | v(256)] per child row
__device__ float g_q[(size_t)16384 * 256];
__device__ float g_aout[(size_t)16384 * 256];
__device__ float g_hattn[(size_t)16384 * 256];
__device__ float g_hu[(size_t)16384 * 1024];        // [h_iou(768) | h_f(256)]
__device__ float g_Wcat1[256 * 1024];
__device__ float g_bcat1[1024];
__device__ float g_Wkv[256 * 512];
__device__ float g_bkv[512];
__device__ float g_Ucat[256 * 1024];
__device__ float g_bUcat[1024];

__device__ __forceinline__ float sigmoidf_(float x) { return 1.0f / (1.0f + expf(-x)); }

// ---------------- weight packing ----------------
__global__ void pack_weights(const float* __restrict__ W_iou, const float* __restrict__ b_iou,
                             const float* __restrict__ W_f,   const float* __restrict__ b_f,
                             const float* __restrict__ Wk,    const float* __restrict__ bk,
                             const float* __restrict__ Wv,    const float* __restrict__ bv,
                             const float* __restrict__ Uiou_w,const float* __restrict__ Uiou_b,
                             const float* __restrict__ Uf_w,  const float* __restrict__ Uf_b)
{
    int idx = blockIdx.x * blockDim.x + threadIdx.x;
    if (idx >= 256 * 1024) return;
    int r = idx >> 10, c = idx & 1023;
    g_Wcat1[idx] = (c < 768) ? W_iou[r * 768 + c] : W_f[r * 256 + (c - 768)];
    g_Ucat[idx]  = (c < 768) ? Uiou_w[r * 768 + c] : Uf_w[r * 256 + (c - 768)];
    if (c < 512) g_Wkv[r * 512 + c] = (c < 256) ? Wk[r * 256 + c] : Wv[r * 256 + (c - 256)];
    if (r == 0) {
        g_bcat1[c] = (c < 768) ? b_iou[c] : b_f[c - 768];
        g_bUcat[c] = (c < 768) ? Uiou_b[c] : Uf_b[c - 768];
        if (c < 512) g_bkv[c] = (c < 256) ? bk[c] : bv[c - 256];
    }
}

// ---------------- GEMM: C[M,N] = A[M,256] @ W[256,N] + bias[N] ----------------
// A row-major lda=256, W row-major ldw=N, C row-major ldc=N. N % 128 == 0.
#define BM 128
#define BN 128
#define BKK 8
__global__ void __launch_bounds__(256) gemm_k256(const float* __restrict__ A,
                                                 const float* __restrict__ W,
                                                 const float* __restrict__ bias,
                                                 float* __restrict__ C, int M, int N)
{
    __shared__ float As[BKK][BM];
    __shared__ float Bs[BKK][BN];
    int tid = threadIdx.x;
    int row0 = blockIdx.y * BM;
    int col0 = blockIdx.x * BN;
    int a_row = tid >> 1;
    int a_col = (tid & 1) * 4;
    int b_row = tid >> 5;
    int b_col = (tid & 31) * 4;
    int ty = tid >> 4;
    int tx = tid & 15;
    float acc[8][8];
    #pragma unroll
    for (int i = 0; i < 8; i++)
        #pragma unroll
        for (int j = 0; j < 8; j++) acc[i][j] = 0.0f;

    for (int k0 = 0; k0 < 256; k0 += BKK) {
        float4 av;
        if (row0 + a_row < M)
            av = *reinterpret_cast<const float4*>(A + (size_t)(row0 + a_row) * 256 + k0 + a_col);
        else
            av = make_float4(0.f, 0.f, 0.f, 0.f);
        As[a_col + 0][a_row] = av.x;
        As[a_col + 1][a_row] = av.y;
        As[a_col + 2][a_row] = av.z;
        As[a_col + 3][a_row] = av.w;
        float4 wv = *reinterpret_cast<const float4*>(W + (size_t)(k0 + b_row) * N + col0 + b_col);
        *reinterpret_cast<float4*>(&Bs[b_row][b_col]) = wv;
        __syncthreads();
        #pragma unroll
        for (int kk = 0; kk < BKK; kk++) {
            float ra[8], rb[8];
            #pragma unroll
            for (int i = 0; i < 8; i++) ra[i] = As[kk][ty * 8 + i];
            #pragma unroll
            for (int j = 0; j < 8; j++) rb[j] = Bs[kk][tx * 8 + j];
            #pragma unroll
            for (int i = 0; i < 8; i++)
                #pragma unroll
                for (int j = 0; j < 8; j++) acc[i][j] += ra[i] * rb[j];
        }
        __syncthreads();
    }
    #pragma unroll
    for (int i = 0; i < 8; i++) {
        int r = row0 + ty * 8 + i;
        if (r >= M) continue;
        #pragma unroll
        for (int j = 0; j < 8; j += 4) {
            int c = col0 + tx * 8 + j;
            float4 v;
            v.x = acc[i][j + 0] + bias[c + 0];
            v.y = acc[i][j + 1] + bias[c + 1];
            v.z = acc[i][j + 2] + bias[c + 2];
            v.w = acc[i][j + 3] + bias[c + 3];
            *reinterpret_cast<float4*>(C + (size_t)r * N + c) = v;
        }
    }
}

// ---------------- leaf level (l = 8): pure gates from x_iou ----------------
__global__ void leaf_kernel(float* __restrict__ outH, float* __restrict__ outC)
{
    int j = blockIdx.x;
    int d = threadIdx.x;
    int node = LEAF_START + j;
    const float* r = g_xiouf + (size_t)node * 1024;
    float i = r[d], o = r[256 + d], u = r[512 + d];
    float c = sigmoidf_(i) * tanhf(u);
    float h = sigmoidf_(o) * tanhf(c);
    outH[(size_t)node * 256 + d] = h;
    outC[(size_t)node * 256 + d] = c;
}

// ---------------- attention: warp per (node, head), 4 children ----------------
__global__ void attn_kernel(int n)
{
    int j = blockIdx.x;
    int w = threadIdx.x >> 5;   // head 0..7
    int t = threadIdx.x & 31;   // dim within head
    const float scale = 0.17677669529663687f; // 1/sqrt(32)
    float qv = g_q[(size_t)j * 256 + w * 32 + t];
    float logit[4];
    #pragma unroll
    for (int k = 0; k < 4; k++) {
        float kk = g_kv[(size_t)(4 * j + k) * 512 + w * 32 + t];
        float p = qv * kk;
        #pragma unroll
        for (int off = 16; off; off >>= 1) p += __shfl_xor_sync(0xffffffffu, p, off);
        logit[k] = p * scale;
    }
    float m = fmaxf(fmaxf(logit[0], logit[1]), fmaxf(logit[2], logit[3]));
    float e[4], s = 0.f;
    #pragma unroll
    for (int k = 0; k < 4; k++) { e[k] = expf(logit[k] - m); s += e[k]; }
    float inv = 1.0f / s;
    float o = 0.f;
    #pragma unroll
    for (int k = 0; k < 4; k++)
        o += e[k] * inv * g_kv[(size_t)(4 * j + k) * 512 + 256 + w * 32 + t];
    g_aout[(size_t)j * 256 + w * 32 + t] = o;
}

// ---------------- internal-level gates ----------------
__global__ void gate_kernel(float* __restrict__ outH, float* __restrict__ outC,
                            int s0, int cs)
{
    int j = blockIdx.x;
    int d = threadIdx.x;
    int node = s0 + j;
    const float* xr = g_xiouf + (size_t)node * 1024;
    const float* hr = g_hu + (size_t)j * 1024;
    float i = xr[d]       + hr[d];
    float o = xr[256 + d] + hr[256 + d];
    float u = xr[512 + d] + hr[512 + d];
    float f = sigmoidf_(xr[768 + d] + hr[768 + d]);
    float csum = 0.f;
    #pragma unroll
    for (int k = 0; k < 4; k++)
        csum += outC[(size_t)(cs + 4 * j + k) * 256 + d];
    float c = sigmoidf_(i) * tanhf(u) + f * csum;
    float h = sigmoidf_(o) * tanhf(c);
    outH[(size_t)node * 256 + d] = h;
    outC[(size_t)node * 256 + d] = c;
}

// ---------------- host launch ----------------
extern "C" void kernel_launch(void* const* d_in, const int* in_sizes, int n_in,
                              void* d_out, int out_size)
{
    const float* x      = (const float*)d_in[0];
    const float* W_iou  = (const float*)d_in[1];
    const float* b_iou  = (const float*)d_in[2];
    const float* W_f    = (const float*)d_in[3];
    const float* b_f    = (const float*)d_in[4];
    const float* Wq     = (const float*)d_in[5];
    const float* bq     = (const float*)d_in[6];
    const float* Wk     = (const float*)d_in[7];
    const float* bk     = (const float*)d_in[8];
    const float* Wv     = (const float*)d_in[9];
    const float* bv     = (const float*)d_in[10];
    const float* Wl     = (const float*)d_in[11];
    const float* bl     = (const float*)d_in[12];
    const float* Uiou_w = (const float*)d_in[13];
    const float* Uiou_b = (const float*)d_in[14];
    const float* Uf_w   = (const float*)d_in[15];
    const float* Uf_b   = (const float*)d_in[16];

    float* outH = (float*)d_out;
    float* outC = outH + (size_t)N_NODES * 256;

    float *p_xiouf, *p_kv, *p_q, *p_aout, *p_hattn, *p_hu;
    float *p_W1, *p_b1, *p_Wkv, *p_bkv, *p_Uc, *p_bU;
    cudaGetSymbolAddress((void**)&p_xiouf, g_xiouf);
    cudaGetSymbolAddress((void**)&p_kv,    g_kv);
    cudaGetSymbolAddress((void**)&p_q,     g_q);
    cudaGetSymbolAddress((void**)&p_aout,  g_aout);
    cudaGetSymbolAddress((void**)&p_hattn, g_hattn);
    cudaGetSymbolAddress((void**)&p_hu,    g_hu);
    cudaGetSymbolAddress((void**)&p_W1,    g_Wcat1);
    cudaGetSymbolAddress((void**)&p_b1,    g_bcat1);
    cudaGetSymbolAddress((void**)&p_Wkv,   g_Wkv);
    cudaGetSymbolAddress((void**)&p_bkv,   g_bkv);
    cudaGetSymbolAddress((void**)&p_Uc,    g_Ucat);
    cudaGetSymbolAddress((void**)&p_bU,    g_bUcat);

    // starts[l] = (4^l - 1)/3
    static const int starts[LEVELS + 1] =
        {0, 1, 5, 21, 85, 341, 1365, 5461, 21845, 87381};

    pack_weights<<<(256 * 1024 + 255) / 256, 256>>>(
        W_iou, b_iou, W_f, b_f, Wk, bk, Wv, bv, Uiou_w, Uiou_b, Uf_w, Uf_b);

    // x_iou | x_f for all nodes
    {
        dim3 grid(1024 / BN, (N_NODES + BM - 1) / BM);
        gemm_k256<<<grid, 256>>>(x, p_W1, p_b1, p_xiouf, N_NODES, 1024);
    }

    leaf_kernel<<<LEAF_N, 256>>>(outH, outC);

    for (int l = LEVELS - 2; l >= 0; --l) {
        int n  = 1 << (2 * l);      // 4^l
        int s0 = starts[l];
        int cs = starts[l + 1];
        int nc = 4 * n;

        // k|v for all children of this level
        {
            dim3 grid(512 / BN, (nc + BM - 1) / BM);
            gemm_k256<<<grid, 256>>>(outH + (size_t)cs * 256, p_Wkv, p_bkv, p_kv, nc, 512);
        }
        // q from x
        {
            dim3 grid(256 / BN, (n + BM - 1) / BM);
            gemm_k256<<<grid, 256>>>(x + (size_t)s0 * 256, Wq, bq, p_q, n, 256);
        }
        attn_kernel<<<n, 256>>>(n);
        // h_attn = aout @ Wl + bl
        {
            dim3 grid(256 / BN, (n + BM - 1) / BM);
            gemm_k256<<<grid, 256>>>(p_aout, Wl, bl, p_hattn, n, 256);
        }
        // h_iou | h_f
        {
            dim3 grid(1024 / BN, (n + BM - 1) / BM);
            gemm_k256<<<grid, 256>>>(p_hattn, p_Uc, p_bU, p_hu, n, 1024);
        }
        gate_kernel<<<n, 256>>>(outH, outC, s0, cs);
    }
}

// round 2
// speedup vs baseline: 2.3372x; 2.3372x over previous
#include <cuda_runtime.h>
#include <math.h>
#include <stdint.h>

#define KARY 4
#define LEVELS 9
#define N_NODES 87381          // (4^9-1)/3
#define LEAF_START 21845       // starts[8]
#define LEAF_N 65536

// ---------------- scratch (device globals: allocation-free rule) ----------------
__device__ float g_xiouf[(size_t)N_NODES * 1024];   // [iou(768) | f(256)] per node
__device__ float g_kv[(size_t)65536 * 512];         // [k(256) | v(256)] per child row
__device__ float g_q[(size_t)16384 * 256];
__device__ float g_aout[(size_t)16384 * 256];
__device__ float g_hattn[(size_t)16384 * 256];
__device__ float g_hu[(size_t)16384 * 1024];        // [h_iou(768) | h_f(256)]
__device__ float g_Wcat1[256 * 1024];
__device__ float g_bcat1[1024];
__device__ float g_Wkv[256 * 512];
__device__ float g_bkv[512];
__device__ float g_Ucat[256 * 1024];
__device__ float g_bUcat[1024];

__device__ __forceinline__ float sigmoidf_(float x) { return 1.0f / (1.0f + expf(-x)); }

__device__ __forceinline__ uint32_t f2tf32(float v) {
    uint32_t r;
    asm("cvt.rna.tf32.f32 %0, %1;" : "=r"(r) : "f"(v));
    return r;
}

__device__ __forceinline__ void mma_tf32(float c[4],
                                         uint32_t a0, uint32_t a1, uint32_t a2, uint32_t a3,
                                         uint32_t b0, uint32_t b1) {
    asm volatile("mma.sync.aligned.m16n8k8.row.col.f32.tf32.tf32.f32 "
                 "{%0,%1,%2,%3}, {%4,%5,%6,%7}, {%8,%9}, {%0,%1,%2,%3};\n"
                 : "+f"(c[0]), "+f"(c[1]), "+f"(c[2]), "+f"(c[3])
                 : "r"(a0), "r"(a1), "r"(a2), "r"(a3), "r"(b0), "r"(b1));
}

// ---------------- weight packing ----------------
__global__ void pack_weights(const float* __restrict__ W_iou, const float* __restrict__ b_iou,
                             const float* __restrict__ W_f,   const float* __restrict__ b_f,
                             const float* __restrict__ Wk,    const float* __restrict__ bk,
                             const float* __restrict__ Wv,    const float* __restrict__ bv,
                             const float* __restrict__ Uiou_w,const float* __restrict__ Uiou_b,
                             const float* __restrict__ Uf_w,  const float* __restrict__ Uf_b)
{
    int idx = blockIdx.x * blockDim.x + threadIdx.x;
    if (idx >= 256 * 1024) return;
    int r = idx >> 10, c = idx & 1023;
    g_Wcat1[idx] = (c < 768) ? W_iou[r * 768 + c] : W_f[r * 256 + (c - 768)];
    g_Ucat[idx]  = (c < 768) ? Uiou_w[r * 768 + c] : Uf_w[r * 256 + (c - 768)];
    if (c < 512) g_Wkv[r * 512 + c] = (c < 256) ? Wk[r * 256 + c] : Wv[r * 256 + (c - 256)];
    if (r == 0) {
        g_bcat1[c] = (c < 768) ? b_iou[c] : b_f[c - 768];
        g_bUcat[c] = (c < 768) ? Uiou_b[c] : Uf_b[c - 768];
        if (c < 512) g_bkv[c] = (c < 256) ? bk[c] : bv[c - 256];
    }
}

// ---------------- TF32 tensor-core GEMM ----------------
// C[M,N] = A[M,256] @ W[256,N] + bias[N]. N % 128 == 0.
// Block 128x128x32, 8 warps; warp tile 64x32 (4x4 m16n8k8 mmas).
#define TBM 128
#define TBN 128
#define TBK 32
#define SPAD 136  // 128 + 8 pad: conflict-free fragment reads

__global__ void __launch_bounds__(256) gemm_tf32(const float* __restrict__ A,
                                                 const float* __restrict__ W,
                                                 const float* __restrict__ bias,
                                                 float* __restrict__ C, int M, int N)
{
    __shared__ uint32_t As[TBK][SPAD];  // [k][m]
    __shared__ uint32_t Bs[TBK][SPAD];  // [k][n]

    int tid  = threadIdx.x;
    int lane = tid & 31;
    int warp = tid >> 5;
    int wr = warp >> 2;          // 0..1 : warp row (64 rows each)
    int wc = warp & 3;           // 0..3 : warp col (32 cols each)
    int gid = lane >> 2;         // 0..7
    int tig = lane & 3;          // 0..3
    int row0 = blockIdx.y * TBM;
    int col0 = blockIdx.x * TBN;

    float acc[4][4][4];
    #pragma unroll
    for (int mi = 0; mi < 4; mi++)
        #pragma unroll
        for (int ni = 0; ni < 4; ni++)
            #pragma unroll
            for (int t = 0; t < 4; t++) acc[mi][ni][t] = 0.0f;

    for (int k0 = 0; k0 < 256; k0 += TBK) {
        // Load A tile: 128 rows x 32 k -> As[k][m] (transposed store)
        #pragma unroll
        for (int i = 0; i < 4; i++) {
            int f  = tid + i * 256;     // float4 index, 0..1023
            int ar = f >> 3;            // row within tile
            int ak = (f & 7) * 4;       // k within tile
            float4 v;
            if (row0 + ar < M)
                v = *reinterpret_cast<const float4*>(A + (size_t)(row0 + ar) * 256 + k0 + ak);
            else
                v = make_float4(0.f, 0.f, 0.f, 0.f);
            As[ak + 0][ar] = f2tf32(v.x);
            As[ak + 1][ar] = f2tf32(v.y);
            As[ak + 2][ar] = f2tf32(v.z);
            As[ak + 3][ar] = f2tf32(v.w);
        }
        // Load B tile: 32 k x 128 n -> Bs[k][n]
        #pragma unroll
        for (int i = 0; i < 4; i++) {
            int f  = tid + i * 256;
            int bk_ = f >> 5;           // k within tile
            int bn  = (f & 31) * 4;     // n within tile
            float4 v = *reinterpret_cast<const float4*>(W + (size_t)(k0 + bk_) * N + col0 + bn);
            uint4 u;
            u.x = f2tf32(v.x); u.y = f2tf32(v.y); u.z = f2tf32(v.z); u.w = f2tf32(v.w);
            *reinterpret_cast<uint4*>(&Bs[bk_][bn]) = u;
        }
        __syncthreads();

        #pragma unroll
        for (int kk = 0; kk < TBK; kk += 8) {
            uint32_t af[4][4];
            #pragma unroll
            for (int mi = 0; mi < 4; mi++) {
                int rb = wr * 64 + mi * 16;
                af[mi][0] = As[kk + tig][rb + gid];
                af[mi][1] = As[kk + tig][rb + gid + 8];
                af[mi][2] = As[kk + tig + 4][rb + gid];
                af[mi][3] = As[kk + tig + 4][rb + gid + 8];
            }
            uint32_t bf[4][2];
            #pragma unroll
            for (int ni = 0; ni < 4; ni++) {
                int cb = wc * 32 + ni * 8;
                bf[ni][0] = Bs[kk + tig][cb + gid];
                bf[ni][1] = Bs[kk + tig + 4][cb + gid];
            }
            #pragma unroll
            for (int mi = 0; mi < 4; mi++)
                #pragma unroll
                for (int ni = 0; ni < 4; ni++)
                    mma_tf32(acc[mi][ni],
                             af[mi][0], af[mi][1], af[mi][2], af[mi][3],
                             bf[ni][0], bf[ni][1]);
        }
        __syncthreads();
    }

    // Epilogue: add bias, write C
    #pragma unroll
    for (int mi = 0; mi < 4; mi++) {
        int rbase = row0 + wr * 64 + mi * 16 + gid;
        #pragma unroll
        for (int ni = 0; ni < 4; ni++) {
            int c = col0 + wc * 32 + ni * 8 + 2 * tig;
            float b0 = bias[c], b1 = bias[c + 1];
            if (rbase < M) {
                float2 v0 = make_float2(acc[mi][ni][0] + b0, acc[mi][ni][1] + b1);
                *reinterpret_cast<float2*>(C + (size_t)rbase * N + c) = v0;
            }
            if (rbase + 8 < M) {
                float2 v1 = make_float2(acc[mi][ni][2] + b0, acc[mi][ni][3] + b1);
                *reinterpret_cast<float2*>(C + (size_t)(rbase + 8) * N + c) = v1;
            }
        }
    }
}

// ---------------- leaf level (l = 8): pure gates from x_iou ----------------
__global__ void leaf_kernel(float* __restrict__ outH, float* __restrict__ outC)
{
    int j = blockIdx.x;
    int d = threadIdx.x;
    int node = LEAF_START + j;
    const float* r = g_xiouf + (size_t)node * 1024;
    float i = r[d], o = r[256 + d], u = r[512 + d];
    float c = sigmoidf_(i) * tanhf(u);
    float h = sigmoidf_(o) * tanhf(c);
    outH[(size_t)node * 256 + d] = h;
    outC[(size_t)node * 256 + d] = c;
}

// ---------------- attention: warp per (node, head), 4 children ----------------
__global__ void attn_kernel(int n)
{
    int j = blockIdx.x;
    int w = threadIdx.x >> 5;   // head 0..7
    int t = threadIdx.x & 31;   // dim within head
    const float scale = 0.17677669529663687f; // 1/sqrt(32)
    float qv = g_q[(size_t)j * 256 + w * 32 + t];
    float logit[4];
    #pragma unroll
    for (int k = 0; k < 4; k++) {
        float kk = g_kv[(size_t)(4 * j + k) * 512 + w * 32 + t];
        float p = qv * kk;
        #pragma unroll
        for (int off = 16; off; off >>= 1) p += __shfl_xor_sync(0xffffffffu, p, off);
        logit[k] = p * scale;
    }
    float m = fmaxf(fmaxf(logit[0], logit[1]), fmaxf(logit[2], logit[3]));
    float e[4], s = 0.f;
    #pragma unroll
    for (int k = 0; k < 4; k++) { e[k] = expf(logit[k] - m); s += e[k]; }
    float inv = 1.0f / s;
    float o = 0.f;
    #pragma unroll
    for (int k = 0; k < 4; k++)
        o += e[k] * inv * g_kv[(size_t)(4 * j + k) * 512 + 256 + w * 32 + t];
    g_aout[(size_t)j * 256 + w * 32 + t] = o;
}

// ---------------- internal-level gates ----------------
__global__ void gate_kernel(float* __restrict__ outH, float* __restrict__ outC,
                            int s0, int cs)
{
    int j = blockIdx.x;
    int d = threadIdx.x;
    int node = s0 + j;
    const float* xr = g_xiouf + (size_t)node * 1024;
    const float* hr = g_hu + (size_t)j * 1024;
    float i = xr[d]       + hr[d];
    float o = xr[256 + d] + hr[256 + d];
    float u = xr[512 + d] + hr[512 + d];
    float f = sigmoidf_(xr[768 + d] + hr[768 + d]);
    float csum = 0.f;
    #pragma unroll
    for (int k = 0; k < 4; k++)
        csum += outC[(size_t)(cs + 4 * j + k) * 256 + d];
    float c = sigmoidf_(i) * tanhf(u) + f * csum;
    float h = sigmoidf_(o) * tanhf(c);
    outH[(size_t)node * 256 + d] = h;
    outC[(size_t)node * 256 + d] = c;
}

// ---------------- host launch ----------------
extern "C" void kernel_launch(void* const* d_in, const int* in_sizes, int n_in,
                              void* d_out, int out_size)
{
    const float* x      = (const float*)d_in[0];
    const float* W_iou  = (const float*)d_in[1];
    const float* b_iou  = (const float*)d_in[2];
    const float* W_f    = (const float*)d_in[3];
    const float* b_f    = (const float*)d_in[4];
    const float* Wq     = (const float*)d_in[5];
    const float* bq     = (const float*)d_in[6];
    const float* Wk     = (const float*)d_in[7];
    const float* bk     = (const float*)d_in[8];
    const float* Wv     = (const float*)d_in[9];
    const float* bv     = (const float*)d_in[10];
    const float* Wl     = (const float*)d_in[11];
    const float* bl     = (const float*)d_in[12];
    const float* Uiou_w = (const float*)d_in[13];
    const float* Uiou_b = (const float*)d_in[14];
    const float* Uf_w   = (const float*)d_in[15];
    const float* Uf_b   = (const float*)d_in[16];

    float* outH = (float*)d_out;
    float* outC = outH + (size_t)N_NODES * 256;

    float *p_xiouf, *p_kv, *p_q, *p_aout, *p_hattn, *p_hu;
    float *p_W1, *p_b1, *p_Wkv, *p_bkv, *p_Uc, *p_bU;
    cudaGetSymbolAddress((void**)&p_xiouf, g_xiouf);
    cudaGetSymbolAddress((void**)&p_kv,    g_kv);
    cudaGetSymbolAddress((void**)&p_q,     g_q);
    cudaGetSymbolAddress((void**)&p_aout,  g_aout);
    cudaGetSymbolAddress((void**)&p_hattn, g_hattn);
    cudaGetSymbolAddress((void**)&p_hu,    g_hu);
    cudaGetSymbolAddress((void**)&p_W1,    g_Wcat1);
    cudaGetSymbolAddress((void**)&p_b1,    g_bcat1);
    cudaGetSymbolAddress((void**)&p_Wkv,   g_Wkv);
    cudaGetSymbolAddress((void**)&p_bkv,   g_bkv);
    cudaGetSymbolAddress((void**)&p_Uc,    g_Ucat);
    cudaGetSymbolAddress((void**)&p_bU,    g_bUcat);

    // starts[l] = (4^l - 1)/3
    static const int starts[LEVELS + 1] =
        {0, 1, 5, 21, 85, 341, 1365, 5461, 21845, 87381};

    pack_weights<<<(256 * 1024 + 255) / 256, 256>>>(
        W_iou, b_iou, W_f, b_f, Wk, bk, Wv, bv, Uiou_w, Uiou_b, Uf_w, Uf_b);

    // x_iou | x_f for all nodes
    {
        dim3 grid(1024 / TBN, (N_NODES + TBM - 1) / TBM);
        gemm_tf32<<<grid, 256>>>(x, p_W1, p_b1, p_xiouf, N_NODES, 1024);
    }

    leaf_kernel<<<LEAF_N, 256>>>(outH, outC);

    for (int l = LEVELS - 2; l >= 0; --l) {
        int n  = 1 << (2 * l);      // 4^l
        int s0 = starts[l];
        int cs = starts[l + 1];
        int nc = 4 * n;

        // k|v for all children of this level
        {
            dim3 grid(512 / TBN, (nc + TBM - 1) / TBM);
            gemm_tf32<<<grid, 256>>>(outH + (size_t)cs * 256, p_Wkv, p_bkv, p_kv, nc, 512);
        }
        // q from x
        {
            dim3 grid(256 / TBN, (n + TBM - 1) / TBM);
            gemm_tf32<<<grid, 256>>>(x + (size_t)s0 * 256, Wq, bq, p_q, n, 256);
        }
        attn_kernel<<<n, 256>>>(n);
        // h_attn = aout @ Wl + bl
        {
            dim3 grid(256 / TBN, (n + TBM - 1) / TBM);
            gemm_tf32<<<grid, 256>>>(p_aout, Wl, bl, p_hattn, n, 256);
        }
        // h_iou | h_f
        {
            dim3 grid(1024 / TBN, (n + TBM - 1) / TBM);
            gemm_tf32<<<grid, 256>>>(p_hattn, p_Uc, p_bU, p_hu, n, 1024);
        }
        gate_kernel<<<n, 256>>>(outH, outC, s0, cs);
    }
}

// round 3
// speedup vs baseline: 2.9621x; 1.2674x over previous
#include <cuda_runtime.h>
#include <math.h>
#include <stdint.h>

#define KARY 4
#define LEVELS 9
#define N_NODES 87381          // (4^9-1)/3
#define LEAF_START 21845       // starts[8]
#define LEAF_N 65536

// ---------------- scratch (device globals: allocation-free rule) ----------------
__device__ float g_xiouf[(size_t)N_NODES * 1024];   // [iou(768) | f(256)] per node
__device__ float g_kv[(size_t)65536 * 512];         // [k(256) | v(256)] per child row
__device__ float g_q[(size_t)16384 * 256];
__device__ float g_aout[(size_t)16384 * 256];
__device__ float g_hattn[(size_t)16384 * 256];
__device__ float g_hu[(size_t)16384 * 1024];        // [h_iou(768) | h_f(256)]
// transposed packed weights: [N][256] row-major
__device__ float g_Wcat1T[1024 * 256];
__device__ float g_bcat1[1024];
__device__ float g_WkvT[512 * 256];
__device__ float g_bkv[512];
__device__ float g_UcatT[1024 * 256];
__device__ float g_bUcat[1024];
__device__ float g_WqT[256 * 256];
__device__ float g_WlT[256 * 256];

__device__ __forceinline__ float sigmoidf_(float x) { return 1.0f / (1.0f + expf(-x)); }

__device__ __forceinline__ uint32_t f2tf32(float v) {
    uint32_t r;
    asm("cvt.rna.tf32.f32 %0, %1;" : "=r"(r) : "f"(v));
    return r;
}

__device__ __forceinline__ void mma_tf32(float c[4],
                                         uint32_t a0, uint32_t a1, uint32_t a2, uint32_t a3,
                                         uint32_t b0, uint32_t b1) {
    asm volatile("mma.sync.aligned.m16n8k8.row.col.f32.tf32.tf32.f32 "
                 "{%0,%1,%2,%3}, {%4,%5,%6,%7}, {%8,%9}, {%0,%1,%2,%3};\n"
                 : "+f"(c[0]), "+f"(c[1]), "+f"(c[2]), "+f"(c[3])
                 : "r"(a0), "r"(a1), "r"(a2), "r"(a3), "r"(b0), "r"(b1));
}

__device__ __forceinline__ void ldsm_x4(uint32_t& r0, uint32_t& r1, uint32_t& r2, uint32_t& r3,
                                        uint32_t addr) {
    asm volatile("ldmatrix.sync.aligned.m8n8.x4.shared.b16 {%0,%1,%2,%3}, [%4];"
                 : "=r"(r0), "=r"(r1), "=r"(r2), "=r"(r3) : "r"(addr));
}

// ---------------- weight packing (transpose to [N][256]) ----------------
__global__ void pack_weights(const float* __restrict__ W_iou, const float* __restrict__ b_iou,
                             const float* __restrict__ W_f,   const float* __restrict__ b_f,
                             const float* __restrict__ Wq,
                             const float* __restrict__ Wk,    const float* __restrict__ bk,
                             const float* __restrict__ Wv,    const float* __restrict__ bv,
                             const float* __restrict__ Wl,
                             const float* __restrict__ Uiou_w,const float* __restrict__ Uiou_b,
                             const float* __restrict__ Uf_w,  const float* __restrict__ Uf_b)
{
    int idx = blockIdx.x * blockDim.x + threadIdx.x;
    if (idx >= 256 * 1024) return;
    int r = idx >> 10, c = idx & 1023;   // r = k row, c = output col
    float w1 = (c < 768) ? W_iou[r * 768 + c] : W_f[r * 256 + (c - 768)];
    float wu = (c < 768) ? Uiou_w[r * 768 + c] : Uf_w[r * 256 + (c - 768)];
    g_Wcat1T[c * 256 + r] = w1;
    g_UcatT[c * 256 + r]  = wu;
    if (c < 512) {
        float wk = (c < 256) ? Wk[r * 256 + c] : Wv[r * 256 + (c - 256)];
        g_WkvT[c * 256 + r] = wk;
    }
    if (c < 256) {
        g_WqT[c * 256 + r] = Wq[r * 256 + c];
        g_WlT[c * 256 + r] = Wl[r * 256 + c];
    }
    if (r == 0) {
        g_bcat1[c] = (c < 768) ? b_iou[c] : b_f[c - 768];
        g_bUcat[c] = (c < 768) ? Uiou_b[c] : Uf_b[c - 768];
        if (c < 512) g_bkv[c] = (c < 256) ? bk[c] : bv[c - 256];
    }
}

// ---------------- TF32 tensor-core GEMM with ldmatrix ----------------
// C[M,N] = A[M,256] @ Bt[N,256]^T + bias[N].  N % 128 == 0.
// Block 128x128x32, 4 warps; warp tile 64x64 (4x8 m16n8k8 mmas per k8).
#define SROW 36    // 32 k-words + 4 pad -> ldmatrix rows hit banks 4r mod 32

__global__ void __launch_bounds__(128) gemm_tf32(const float* __restrict__ A,
                                                 const float* __restrict__ Bt,
                                                 const float* __restrict__ bias,
                                                 float* __restrict__ C, int M, int N)
{
    __shared__ uint32_t As[128][SROW];
    __shared__ uint32_t Bs[128][SROW];

    int tid  = threadIdx.x;
    int lane = tid & 31;
    int warp = tid >> 5;
    int wr = warp >> 1;          // 0..1
    int wc = warp & 1;           // 0..1
    int g  = lane >> 3;          // 0..3 (ldmatrix tile group)
    int r8 = lane & 7;
    int gid = lane >> 2;         // 0..7
    int tig = lane & 3;          // 0..3
    int row0 = blockIdx.y * 128;
    int col0 = blockIdx.x * 128;

    // ldmatrix base addresses (word offsets computed in bytes)
    uint32_t as_base = (uint32_t)__cvta_generic_to_shared(&As[0][0]);
    uint32_t bs_base = (uint32_t)__cvta_generic_to_shared(&Bs[0][0]);
    // A tiles: rows m0 + (g&1)*8 + r8, col offset (g>>1)*4
    uint32_t a_addr[4];
    #pragma unroll
    for (int mi = 0; mi < 4; mi++) {
        int row = wr * 64 + mi * 16 + ((g & 1) << 3) + r8;
        a_addr[mi] = as_base + (row * SROW + ((g >> 1) << 2)) * 4;
    }
    // B tile pairs: rows n0 + (g>>1)*8 + r8, col offset (g&1)*4
    uint32_t b_addr[4];
    #pragma unroll
    for (int np = 0; np < 4; np++) {
        int row = wc * 64 + np * 16 + ((g >> 1) << 3) + r8;
        b_addr[np] = bs_base + (row * SROW + ((g & 1) << 2)) * 4;
    }

    float acc[4][8][4];
    #pragma unroll
    for (int mi = 0; mi < 4; mi++)
        #pragma unroll
        for (int ni = 0; ni < 8; ni++)
            #pragma unroll
            for (int t = 0; t < 4; t++) acc[mi][ni][t] = 0.0f;

    for (int k0 = 0; k0 < 256; k0 += 32) {
        // Load tiles: each thread 8 float4 per matrix.
        #pragma unroll
        for (int i = 0; i < 8; i++) {
            int f  = tid + i * 128;       // 0..1023
            int rw = f >> 3;              // row in tile
            int kq = (f & 7) << 2;        // k word offset
            float4 av;
            if (row0 + rw < M)
                av = *reinterpret_cast<const float4*>(A + (size_t)(row0 + rw) * 256 + k0 + kq);
            else
                av = make_float4(0.f, 0.f, 0.f, 0.f);
            uint4 ua;
            ua.x = f2tf32(av.x); ua.y = f2tf32(av.y); ua.z = f2tf32(av.z); ua.w = f2tf32(av.w);
            *reinterpret_cast<uint4*>(&As[rw][kq]) = ua;
            float4 bv = *reinterpret_cast<const float4*>(Bt + (size_t)(col0 + rw) * 256 + k0 + kq);
            uint4 ub;
            ub.x = f2tf32(bv.x); ub.y = f2tf32(bv.y); ub.z = f2tf32(bv.z); ub.w = f2tf32(bv.w);
            *reinterpret_cast<uint4*>(&Bs[rw][kq]) = ub;
        }
        __syncthreads();

        #pragma unroll
        for (int kk = 0; kk < 32; kk += 8) {
            uint32_t af[4][4];
            #pragma unroll
            for (int mi = 0; mi < 4; mi++)
                ldsm_x4(af[mi][0], af[mi][1], af[mi][2], af[mi][3], a_addr[mi] + kk * 4);
            uint32_t bf[8][2];
            #pragma unroll
            for (int np = 0; np < 4; np++)
                ldsm_x4(bf[2 * np][0], bf[2 * np][1], bf[2 * np + 1][0], bf[2 * np + 1][1],
                        b_addr[np] + kk * 4);
            #pragma unroll
            for (int mi = 0; mi < 4; mi++)
                #pragma unroll
                for (int ni = 0; ni < 8; ni++)
                    mma_tf32(acc[mi][ni],
                             af[mi][0], af[mi][1], af[mi][2], af[mi][3],
                             bf[ni][0], bf[ni][1]);
        }
        __syncthreads();
    }

    // Epilogue: add bias, write C
    #pragma unroll
    for (int mi = 0; mi < 4; mi++) {
        int rbase = row0 + wr * 64 + mi * 16 + gid;
        #pragma unroll
        for (int ni = 0; ni < 8; ni++) {
            int c = col0 + wc * 64 + ni * 8 + 2 * tig;
            float b0 = bias[c], b1 = bias[c + 1];
            if (rbase < M) {
                float2 v0 = make_float2(acc[mi][ni][0] + b0, acc[mi][ni][1] + b1);
                *reinterpret_cast<float2*>(C + (size_t)rbase * N + c) = v0;
            }
            if (rbase + 8 < M) {
                float2 v1 = make_float2(acc[mi][ni][2] + b0, acc[mi][ni][3] + b1);
                *reinterpret_cast<float2*>(C + (size_t)(rbase + 8) * N + c) = v1;
            }
        }
    }
}

// ---------------- leaf level (l = 8): pure gates from x_iou ----------------
__global__ void leaf_kernel(float* __restrict__ outH, float* __restrict__ outC)
{
    int j = blockIdx.x;
    int d = threadIdx.x;
    int node = LEAF_START + j;
    const float* r = g_xiouf + (size_t)node * 1024;
    float i = r[d], o = r[256 + d], u = r[512 + d];
    float c = sigmoidf_(i) * tanhf(u);
    float h = sigmoidf_(o) * tanhf(c);
    outH[(size_t)node * 256 + d] = h;
    outC[(size_t)node * 256 + d] = c;
}

// ---------------- attention: warp per (node, head), 4 children ----------------
__global__ void attn_kernel(int n)
{
    int j = blockIdx.x;
    int w = threadIdx.x >> 5;   // head 0..7
    int t = threadIdx.x & 31;   // dim within head
    const float scale = 0.17677669529663687f; // 1/sqrt(32)
    float qv = g_q[(size_t)j * 256 + w * 32 + t];
    float logit[4];
    #pragma unroll
    for (int k = 0; k < 4; k++) {
        float kk = g_kv[(size_t)(4 * j + k) * 512 + w * 32 + t];
        float p = qv * kk;
        #pragma unroll
        for (int off = 16; off; off >>= 1) p += __shfl_xor_sync(0xffffffffu, p, off);
        logit[k] = p * scale;
    }
    float m = fmaxf(fmaxf(logit[0], logit[1]), fmaxf(logit[2], logit[3]));
    float e[4], s = 0.f;
    #pragma unroll
    for (int k = 0; k < 4; k++) { e[k] = expf(logit[k] - m); s += e[k]; }
    float inv = 1.0f / s;
    float o = 0.f;
    #pragma unroll
    for (int k = 0; k < 4; k++)
        o += e[k] * inv * g_kv[(size_t)(4 * j + k) * 512 + 256 + w * 32 + t];
    g_aout[(size_t)j * 256 + w * 32 + t] = o;
}

// ---------------- internal-level gates ----------------
__global__ void gate_kernel(float* __restrict__ outH, float* __restrict__ outC,
                            int s0, int cs)
{
    int j = blockIdx.x;
    int d = threadIdx.x;
    int node = s0 + j;
    const float* xr = g_xiouf + (size_t)node * 1024;
    const float* hr = g_hu + (size_t)j * 1024;
    float i = xr[d]       + hr[d];
    float o = xr[256 + d] + hr[256 + d];
    float u = xr[512 + d] + hr[512 + d];
    float f = sigmoidf_(xr[768 + d] + hr[768 + d]);
    float csum = 0.f;
    #pragma unroll
    for (int k = 0; k < 4; k++)
        csum += outC[(size_t)(cs + 4 * j + k) * 256 + d];
    float c = sigmoidf_(i) * tanhf(u) + f * csum;
    float h = sigmoidf_(o) * tanhf(c);
    outH[(size_t)node * 256 + d] = h;
    outC[(size_t)node * 256 + d] = c;
}

// ---------------- host launch ----------------
extern "C" void kernel_launch(void* const* d_in, const int* in_sizes, int n_in,
                              void* d_out, int out_size)
{
    const float* x      = (const float*)d_in[0];
    const float* W_iou  = (const float*)d_in[1];
    const float* b_iou  = (const float*)d_in[2];
    const float* W_f    = (const float*)d_in[3];
    const float* b_f    = (const float*)d_in[4];
    const float* Wq     = (const float*)d_in[5];
    const float* bq     = (const float*)d_in[6];
    const float* Wk     = (const float*)d_in[7];
    const float* bk     = (const float*)d_in[8];
    const float* Wv     = (const float*)d_in[9];
    const float* bv     = (const float*)d_in[10];
    const float* Wl     = (const float*)d_in[11];
    const float* bl     = (const float*)d_in[12];
    const float* Uiou_w = (const float*)d_in[13];
    const float* Uiou_b = (const float*)d_in[14];
    const float* Uf_w   = (const float*)d_in[15];
    const float* Uf_b   = (const float*)d_in[16];

    float* outH = (float*)d_out;
    float* outC = outH + (size_t)N_NODES * 256;

    float *p_xiouf, *p_kv, *p_q, *p_aout, *p_hattn, *p_hu;
    float *p_W1, *p_b1, *p_Wkv, *p_bkv, *p_Uc, *p_bU, *p_Wq, *p_Wl;
    cudaGetSymbolAddress((void**)&p_xiouf, g_xiouf);
    cudaGetSymbolAddress((void**)&p_kv,    g_kv);
    cudaGetSymbolAddress((void**)&p_q,     g_q);
    cudaGetSymbolAddress((void**)&p_aout,  g_aout);
    cudaGetSymbolAddress((void**)&p_hattn, g_hattn);
    cudaGetSymbolAddress((void**)&p_hu,    g_hu);
    cudaGetSymbolAddress((void**)&p_W1,    g_Wcat1T);
    cudaGetSymbolAddress((void**)&p_b1,    g_bcat1);
    cudaGetSymbolAddress((void**)&p_Wkv,   g_WkvT);
    cudaGetSymbolAddress((void**)&p_bkv,   g_bkv);
    cudaGetSymbolAddress((void**)&p_Uc,    g_UcatT);
    cudaGetSymbolAddress((void**)&p_bU,    g_bUcat);
    cudaGetSymbolAddress((void**)&p_Wq,    g_WqT);
    cudaGetSymbolAddress((void**)&p_Wl,    g_WlT);

    // starts[l] = (4^l - 1)/3
    static const int starts[LEVELS + 1] =
        {0, 1, 5, 21, 85, 341, 1365, 5461, 21845, 87381};

    pack_weights<<<(256 * 1024 + 255) / 256, 256>>>(
        W_iou, b_iou, W_f, b_f, Wq, Wk, bk, Wv, bv, Wl, Uiou_w, Uiou_b, Uf_w, Uf_b);

    // x_iou | x_f for all nodes
    {
        dim3 grid(1024 / 128, (N_NODES + 127) / 128);
        gemm_tf32<<<grid, 128>>>(x, p_W1, p_b1, p_xiouf, N_NODES, 1024);
    }

    leaf_kernel<<<LEAF_N, 256>>>(outH, outC);

    for (int l = LEVELS - 2; l >= 0; --l) {
        int n  = 1 << (2 * l);      // 4^l
        int s0 = starts[l];
        int cs = starts[l + 1];
        int nc = 4 * n;

        // k|v for all children of this level
        {
            dim3 grid(512 / 128, (nc + 127) / 128);
            gemm_tf32<<<grid, 128>>>(outH + (size_t)cs * 256, p_Wkv, p_bkv, p_kv, nc, 512);
        }
        // q from x
        {
            dim3 grid(256 / 128, (n + 127) / 128);
            gemm_tf32<<<grid, 128>>>(x + (size_t)s0 * 256, p_Wq, bq, p_q, n, 256);
        }
        attn_kernel<<<n, 256>>>(n);
        // h_attn = aout @ Wl + bl
        {
            dim3 grid(256 / 128, (n + 127) / 128);
            gemm_tf32<<<grid, 128>>>(p_aout, p_Wl, bl, p_hattn, n, 256);
        }
        // h_iou | h_f
        {
            dim3 grid(1024 / 128, (n + 127) / 128);
            gemm_tf32<<<grid, 128>>>(p_hattn, p_Uc, p_bU, p_hu, n, 1024);
        }
        gate_kernel<<<n, 256>>>(outH, outC, s0, cs);
    }
}

// round 4
// speedup vs baseline: 3.7197x; 1.2558x over previous
#include <cuda_runtime.h>
#include <math.h>
#include <stdint.h>

#define LEVELS 9
#define N_NODES 87381          // (4^9-1)/3
#define N_INTERNAL 21845
#define LEAF_START 21845
#define LEAF_N 65536

// ---------------- scratch (device globals: allocation-free rule) ----------------
__device__ float g_xT[(size_t)N_NODES * 256];        // tf32-rounded x
__device__ float g_hT[(size_t)N_NODES * 256];        // tf32-rounded h
__device__ float g_xiouf[(size_t)N_INTERNAL * 1024]; // internal nodes [iou|f]
__device__ float g_xiou_leaf[(size_t)LEAF_N * 768];  // leaf nodes [iou]
__device__ float g_kv[(size_t)65536 * 512];
__device__ float g_q[(size_t)16384 * 256];
__device__ float g_aout[(size_t)16384 * 256];        // tf32-rounded
__device__ float g_hattn[(size_t)16384 * 256];       // tf32-rounded
__device__ float g_hu[(size_t)16384 * 1024];
// transposed packed weights [N][256], pre-rounded to tf32
__device__ float g_Wcat1T[1024 * 256];
__device__ float g_bcat1[1024];
__device__ float g_WkvT[512 * 256];
__device__ float g_bkv[512];
__device__ float g_UcatT[1024 * 256];
__device__ float g_bUcat[1024];
__device__ float g_WqT[256 * 256];
__device__ float g_WlT[256 * 256];

__device__ __forceinline__ float sigmoidf_(float x) { return 1.0f / (1.0f + expf(-x)); }

__device__ __forceinline__ uint32_t f2tf32(float v) {
    uint32_t r;
    asm("cvt.rna.tf32.f32 %0, %1;" : "=r"(r) : "f"(v));
    return r;
}
__device__ __forceinline__ float roundtf(float v) { return __uint_as_float(f2tf32(v)); }

__device__ __forceinline__ void mma_tf32(float c[4],
                                         uint32_t a0, uint32_t a1, uint32_t a2, uint32_t a3,
                                         uint32_t b0, uint32_t b1) {
    asm volatile("mma.sync.aligned.m16n8k8.row.col.f32.tf32.tf32.f32 "
                 "{%0,%1,%2,%3}, {%4,%5,%6,%7}, {%8,%9}, {%0,%1,%2,%3};\n"
                 : "+f"(c[0]), "+f"(c[1]), "+f"(c[2]), "+f"(c[3])
                 : "r"(a0), "r"(a1), "r"(a2), "r"(a3), "r"(b0), "r"(b1));
}

__device__ __forceinline__ void ldsm_x4(uint32_t& r0, uint32_t& r1, uint32_t& r2, uint32_t& r3,
                                        uint32_t addr) {
    asm volatile("ldmatrix.sync.aligned.m8n8.x4.shared.b16 {%0,%1,%2,%3}, [%4];"
                 : "=r"(r0), "=r"(r1), "=r"(r2), "=r"(r3) : "r"(addr));
}

// ---------------- weight packing (transpose to [N][256], round to tf32) ----------------
__global__ void pack_weights(const float* __restrict__ W_iou, const float* __restrict__ b_iou,
                             const float* __restrict__ W_f,   const float* __restrict__ b_f,
                             const float* __restrict__ Wq,
                             const float* __restrict__ Wk,    const float* __restrict__ bk,
                             const float* __restrict__ Wv,    const float* __restrict__ bv,
                             const float* __restrict__ Wl,
                             const float* __restrict__ Uiou_w,const float* __restrict__ Uiou_b,
                             const float* __restrict__ Uf_w,  const float* __restrict__ Uf_b)
{
    int idx = blockIdx.x * blockDim.x + threadIdx.x;
    if (idx >= 256 * 1024) return;
    int r = idx >> 10, c = idx & 1023;
    float w1 = (c < 768) ? W_iou[r * 768 + c] : W_f[r * 256 + (c - 768)];
    float wu = (c < 768) ? Uiou_w[r * 768 + c] : Uf_w[r * 256 + (c - 768)];
    g_Wcat1T[c * 256 + r] = roundtf(w1);
    g_UcatT[c * 256 + r]  = roundtf(wu);
    if (c < 512) {
        float wk = (c < 256) ? Wk[r * 256 + c] : Wv[r * 256 + (c - 256)];
        g_WkvT[c * 256 + r] = roundtf(wk);
    }
    if (c < 256) {
        g_WqT[c * 256 + r] = roundtf(Wq[r * 256 + c]);
        g_WlT[c * 256 + r] = roundtf(Wl[r * 256 + c]);
    }
    if (r == 0) {
        g_bcat1[c] = (c < 768) ? b_iou[c] : b_f[c - 768];
        g_bUcat[c] = (c < 768) ? Uiou_b[c] : Uf_b[c - 768];
        if (c < 512) g_bkv[c] = (c < 256) ? bk[c] : bv[c - 256];
    }
}

// ---------------- x -> tf32-rounded copy ----------------
__global__ void round_x_kernel(const float* __restrict__ x)
{
    size_t i = (size_t)blockIdx.x * blockDim.x + threadIdx.x;
    if (i >= (size_t)N_NODES * 64) return;   // float4 count
    float4 v = reinterpret_cast<const float4*>(x)[i];
    v.x = roundtf(v.x); v.y = roundtf(v.y); v.z = roundtf(v.z); v.w = roundtf(v.w);
    reinterpret_cast<float4*>(g_xT)[i] = v;
}

// ---------------- TF32 tensor-core GEMM, cp.async 3-stage pipeline ----------------
// C[M,N] = A[M,256] @ Bt[N,256]^T + bias[N].  N % 128 == 0. A,Bt pre-rounded tf32.
#define STAGES 3
#define SROW 36
#define STG_WORDS (2 * 128 * SROW)        // A(128 rows) + B(128 rows)
#define STG_BYTES (STG_WORDS * 4)         // 36864
#define GEMM_SMEM (STAGES * STG_BYTES)    // 110592

__device__ __forceinline__ void issue_load(uint32_t sbase, int st,
                                           const float* __restrict__ A,
                                           const float* __restrict__ Bt,
                                           int row0, int col0, int M, int k0,
                                           int rwb, int kq)
{
    uint32_t so = sbase + st * STG_BYTES;
    #pragma unroll
    for (int i = 0; i < 8; i++) {
        int rwi = rwb + 16 * i;
        bool ok = (row0 + rwi) < M;
        uint32_t da = so + (rwi * SROW + kq) * 4;
        const float* ga = A + (size_t)(ok ? (row0 + rwi) : 0) * 256 + k0 + kq;
        int sz = ok ? 16 : 0;
        asm volatile("cp.async.cg.shared.global [%0], [%1], 16, %2;"
                     :: "r"(da), "l"(ga), "r"(sz) : "memory");
        uint32_t db = so + ((128 + rwi) * SROW + kq) * 4;
        const float* gb = Bt + (size_t)(col0 + rwi) * 256 + k0 + kq;
        asm volatile("cp.async.cg.shared.global [%0], [%1], 16;"
                     :: "r"(db), "l"(gb) : "memory");
    }
}

__device__ __forceinline__ void compute_stage(uint32_t soff,
                                              const uint32_t aoff[4], const uint32_t boff[4],
                                              float acc[4][8][4])
{
    #pragma unroll
    for (int kk = 0; kk < 32; kk += 8) {
        uint32_t af[4][4];
        #pragma unroll
        for (int mi = 0; mi < 4; mi++)
            ldsm_x4(af[mi][0], af[mi][1], af[mi][2], af[mi][3], soff + aoff[mi] + kk * 4);
        uint32_t bf[8][2];
        #pragma unroll
        for (int np = 0; np < 4; np++)
            ldsm_x4(bf[2 * np][0], bf[2 * np][1], bf[2 * np + 1][0], bf[2 * np + 1][1],
                    soff + boff[np] + kk * 4);
        #pragma unroll
        for (int mi = 0; mi < 4; mi++)
            #pragma unroll
            for (int ni = 0; ni < 8; ni++)
                mma_tf32(acc[mi][ni],
                         af[mi][0], af[mi][1], af[mi][2], af[mi][3],
                         bf[ni][0], bf[ni][1]);
    }
}

template <bool ROUND>
__global__ void __launch_bounds__(128) gemm_tf32(const float* __restrict__ A,
                                                 const float* __restrict__ Bt,
                                                 const float* __restrict__ bias,
                                                 float* __restrict__ C, int M, int N)
{
    extern __shared__ uint32_t sm[];
    int tid  = threadIdx.x;
    int lane = tid & 31;
    int warp = tid >> 5;
    int wr = warp >> 1, wc = warp & 1;
    int g  = lane >> 3, r8 = lane & 7;
    int gid = lane >> 2, tig = lane & 3;
    int row0 = blockIdx.y * 128;
    int col0 = blockIdx.x * 128;
    int rwb = tid >> 3, kq = (tid & 7) << 2;

    uint32_t sbase = (uint32_t)__cvta_generic_to_shared(sm);
    uint32_t aoff[4], boff[4];
    #pragma unroll
    for (int mi = 0; mi < 4; mi++) {
        int row = wr * 64 + mi * 16 + ((g & 1) << 3) + r8;
        aoff[mi] = (row * SROW + ((g >> 1) << 2)) * 4;
    }
    #pragma unroll
    for (int np = 0; np < 4; np++) {
        int row = 128 + wc * 64 + np * 16 + ((g >> 1) << 3) + r8;
        boff[np] = (row * SROW + ((g & 1) << 2)) * 4;
    }

    float acc[4][8][4];
    #pragma unroll
    for (int mi = 0; mi < 4; mi++)
        #pragma unroll
        for (int ni = 0; ni < 8; ni++)
            #pragma unroll
            for (int t = 0; t < 4; t++) acc[mi][ni][t] = 0.0f;

    issue_load(sbase, 0, A, Bt, row0, col0, M, 0, rwb, kq);
    asm volatile("cp.async.commit_group;" ::: "memory");
    issue_load(sbase, 1, A, Bt, row0, col0, M, 32, rwb, kq);
    asm volatile("cp.async.commit_group;" ::: "memory");

    #pragma unroll
    for (int it = 0; it < 8; it++) {
        asm volatile("cp.async.wait_group 1;" ::: "memory");
        __syncthreads();
        compute_stage(sbase + (it % 3) * STG_BYTES, aoff, boff, acc);
        if (it + 2 < 8)
            issue_load(sbase, (it + 2) % 3, A, Bt, row0, col0, M, (it + 2) * 32, rwb, kq);
        asm volatile("cp.async.commit_group;" ::: "memory");
    }

    #pragma unroll
    for (int mi = 0; mi < 4; mi++) {
        int rbase = row0 + wr * 64 + mi * 16 + gid;
        #pragma unroll
        for (int ni = 0; ni < 8; ni++) {
            int c = col0 + wc * 64 + ni * 8 + 2 * tig;
            float b0 = bias[c], b1 = bias[c + 1];
            if (rbase < M) {
                float v0 = acc[mi][ni][0] + b0, v1 = acc[mi][ni][1] + b1;
                if (ROUND) { v0 = roundtf(v0); v1 = roundtf(v1); }
                *reinterpret_cast<float2*>(C + (size_t)rbase * N + c) = make_float2(v0, v1);
            }
            if (rbase + 8 < M) {
                float v2 = acc[mi][ni][2] + b0, v3 = acc[mi][ni][3] + b1;
                if (ROUND) { v2 = roundtf(v2); v3 = roundtf(v3); }
                *reinterpret_cast<float2*>(C + (size_t)(rbase + 8) * N + c) = make_float2(v2, v3);
            }
        }
    }
}

// ---------------- leaf level: gates from g_xiou_leaf (ld 768), float4 ----------------
__global__ void leaf_kernel(float* __restrict__ outH, float* __restrict__ outC)
{
    int t  = threadIdx.x;
    int jj = blockIdx.x * 4 + (t >> 6);        // leaf-local node 0..65535
    int d  = (t & 63) * 4;
    const float* r = g_xiou_leaf + (size_t)jj * 768;
    float4 iv = *reinterpret_cast<const float4*>(r + d);
    float4 ov = *reinterpret_cast<const float4*>(r + 256 + d);
    float4 uv = *reinterpret_cast<const float4*>(r + 512 + d);
    float4 c4, h4, hr4;
    #pragma unroll
    for (int q = 0; q < 4; q++) {
        float i = (&iv.x)[q], o = (&ov.x)[q], u = (&uv.x)[q];
        float c = sigmoidf_(i) * tanhf(u);
        float h = sigmoidf_(o) * tanhf(c);
        (&c4.x)[q] = c; (&h4.x)[q] = h; (&hr4.x)[q] = roundtf(h);
    }
    size_t base = (size_t)(LEAF_START + jj) * 256 + d;
    *reinterpret_cast<float4*>(outH + base) = h4;
    *reinterpret_cast<float4*>(outC + base) = c4;
    *reinterpret_cast<float4*>(g_hT + base) = hr4;
}

// ---------------- attention: warp per (node, head), 4 children ----------------
__global__ void attn_kernel(int n)
{
    int j = blockIdx.x;
    int w = threadIdx.x >> 5;
    int t = threadIdx.x & 31;
    const float scale = 0.17677669529663687f; // 1/sqrt(32)
    float qv = g_q[(size_t)j * 256 + w * 32 + t];
    float logit[4];
    #pragma unroll
    for (int k = 0; k < 4; k++) {
        float kk = g_kv[(size_t)(4 * j + k) * 512 + w * 32 + t];
        float p = qv * kk;
        #pragma unroll
        for (int off = 16; off; off >>= 1) p += __shfl_xor_sync(0xffffffffu, p, off);
        logit[k] = p * scale;
    }
    float m = fmaxf(fmaxf(logit[0], logit[1]), fmaxf(logit[2], logit[3]));
    float e[4], s = 0.f;
    #pragma unroll
    for (int k = 0; k < 4; k++) { e[k] = expf(logit[k] - m); s += e[k]; }
    float inv = 1.0f / s;
    float o = 0.f;
    #pragma unroll
    for (int k = 0; k < 4; k++)
        o += e[k] * inv * g_kv[(size_t)(4 * j + k) * 512 + 256 + w * 32 + t];
    g_aout[(size_t)j * 256 + w * 32 + t] = roundtf(o);
}

// ---------------- internal-level gates, float4 ----------------
__global__ void gate_kernel(float* __restrict__ outH, float* __restrict__ outC,
                            int s0, int cs, int n)
{
    int t  = threadIdx.x;
    int jj = blockIdx.x * 4 + (t >> 6);
    if (jj >= n) return;
    int d  = (t & 63) * 4;
    int node = s0 + jj;
    const float* xr = g_xiouf + (size_t)node * 1024;
    const float* hr = g_hu + (size_t)jj * 1024;
    float4 i4 = *reinterpret_cast<const float4*>(xr + d);
    float4 o4 = *reinterpret_cast<const float4*>(xr + 256 + d);
    float4 u4 = *reinterpret_cast<const float4*>(xr + 512 + d);
    float4 f4 = *reinterpret_cast<const float4*>(xr + 768 + d);
    float4 hi = *reinterpret_cast<const float4*>(hr + d);
    float4 ho = *reinterpret_cast<const float4*>(hr + 256 + d);
    float4 hu4 = *reinterpret_cast<const float4*>(hr + 512 + d);
    float4 hf = *reinterpret_cast<const float4*>(hr + 768 + d);
    float4 cs4 = make_float4(0.f, 0.f, 0.f, 0.f);
    #pragma unroll
    for (int k = 0; k < 4; k++) {
        float4 cc = *reinterpret_cast<const float4*>(outC + (size_t)(cs + 4 * jj + k) * 256 + d);
        cs4.x += cc.x; cs4.y += cc.y; cs4.z += cc.z; cs4.w += cc.w;
    }
    float4 c4, h4, hr4;
    #pragma unroll
    for (int q = 0; q < 4; q++) {
        float i = (&i4.x)[q] + (&hi.x)[q];
        float o = (&o4.x)[q] + (&ho.x)[q];
        float u = (&u4.x)[q] + (&hu4.x)[q];
        float f = sigmoidf_((&f4.x)[q] + (&hf.x)[q]);
        float c = sigmoidf_(i) * tanhf(u) + f * (&cs4.x)[q];
        float h = sigmoidf_(o) * tanhf(c);
        (&c4.x)[q] = c; (&h4.x)[q] = h; (&hr4.x)[q] = roundtf(h);
    }
    size_t base = (size_t)node * 256 + d;
    *reinterpret_cast<float4*>(outH + base) = h4;
    *reinterpret_cast<float4*>(outC + base) = c4;
    *reinterpret_cast<float4*>(g_hT + base) = hr4;
}

// ---------------- host launch ----------------
extern "C" void kernel_launch(void* const* d_in, const int* in_sizes, int n_in,
                              void* d_out, int out_size)
{
    const float* x      = (const float*)d_in[0];
    const float* W_iou  = (const float*)d_in[1];
    const float* b_iou  = (const float*)d_in[2];
    const float* W_f    = (const float*)d_in[3];
    const float* b_f    = (const float*)d_in[4];
    const float* Wq     = (const float*)d_in[5];
    const float* bq     = (const float*)d_in[6];
    const float* Wk     = (const float*)d_in[7];
    const float* bk     = (const float*)d_in[8];
    const float* Wv     = (const float*)d_in[9];
    const float* bv     = (const float*)d_in[10];
    const float* Wl     = (const float*)d_in[11];
    const float* bl     = (const float*)d_in[12];
    const float* Uiou_w = (const float*)d_in[13];
    const float* Uiou_b = (const float*)d_in[14];
    const float* Uf_w   = (const float*)d_in[15];
    const float* Uf_b   = (const float*)d_in[16];

    float* outH = (float*)d_out;
    float* outC = outH + (size_t)N_NODES * 256;

    static bool attr_set = false;
    if (!attr_set) {
        cudaFuncSetAttribute(gemm_tf32<false>, cudaFuncAttributeMaxDynamicSharedMemorySize, GEMM_SMEM);
        cudaFuncSetAttribute(gemm_tf32<true>,  cudaFuncAttributeMaxDynamicSharedMemorySize, GEMM_SMEM);
        attr_set = true;
    }

    float *p_xT, *p_hT, *p_xiouf, *p_xleaf, *p_kv, *p_q, *p_aout, *p_hattn, *p_hu;
    float *p_W1, *p_b1, *p_Wkv, *p_bkv, *p_Uc, *p_bU, *p_Wq, *p_Wl;
    cudaGetSymbolAddress((void**)&p_xT,    g_xT);
    cudaGetSymbolAddress((void**)&p_hT,    g_hT);
    cudaGetSymbolAddress((void**)&p_xiouf, g_xiouf);
    cudaGetSymbolAddress((void**)&p_xleaf, g_xiou_leaf);
    cudaGetSymbolAddress((void**)&p_kv,    g_kv);
    cudaGetSymbolAddress((void**)&p_q,     g_q);
    cudaGetSymbolAddress((void**)&p_aout,  g_aout);
    cudaGetSymbolAddress((void**)&p_hattn, g_hattn);
    cudaGetSymbolAddress((void**)&p_hu,    g_hu);
    cudaGetSymbolAddress((void**)&p_W1,    g_Wcat1T);
    cudaGetSymbolAddress((void**)&p_b1,    g_bcat1);
    cudaGetSymbolAddress((void**)&p_Wkv,   g_WkvT);
    cudaGetSymbolAddress((void**)&p_bkv,   g_bkv);
    cudaGetSymbolAddress((void**)&p_Uc,    g_UcatT);
    cudaGetSymbolAddress((void**)&p_bU,    g_bUcat);
    cudaGetSymbolAddress((void**)&p_Wq,    g_WqT);
    cudaGetSymbolAddress((void**)&p_Wl,    g_WlT);

    static const int starts[LEVELS + 1] =
        {0, 1, 5, 21, 85, 341, 1365, 5461, 21845, 87381};

    pack_weights<<<(256 * 1024 + 255) / 256, 256>>>(
        W_iou, b_iou, W_f, b_f, Wq, Wk, bk, Wv, bv, Wl, Uiou_w, Uiou_b, Uf_w, Uf_b);
    round_x_kernel<<<(N_NODES * 64 + 255) / 256, 256>>>(x);

    // leaf iou (N=768) and internal iou|f (N=1024)
    {
        dim3 grid(768 / 128, LEAF_N / 128);
        gemm_tf32<false><<<grid, 128, GEMM_SMEM>>>(p_xT + (size_t)LEAF_START * 256,
                                                   p_W1, p_b1, p_xleaf, LEAF_N, 768);
    }
    leaf_kernel<<<LEAF_N / 4, 256>>>(outH, outC);
    {
        dim3 grid(1024 / 128, (N_INTERNAL + 127) / 128);
        gemm_tf32<false><<<grid, 128, GEMM_SMEM>>>(p_xT, p_W1, p_b1, p_xiouf, N_INTERNAL, 1024);
    }

    for (int l = LEVELS - 2; l >= 0; --l) {
        int n  = 1 << (2 * l);
        int s0 = starts[l];
        int cs = starts[l + 1];
        int nc = 4 * n;

        {
            dim3 grid(512 / 128, (nc + 127) / 128);
            gemm_tf32<false><<<grid, 128, GEMM_SMEM>>>(p_hT + (size_t)cs * 256,
                                                       p_Wkv, p_bkv, p_kv, nc, 512);
        }
        {
            dim3 grid(256 / 128, (n + 127) / 128);
            gemm_tf32<false><<<grid, 128, GEMM_SMEM>>>(p_xT + (size_t)s0 * 256,
                                                       p_Wq, bq, p_q, n, 256);
        }
        attn_kernel<<<n, 256>>>(n);
        {
            dim3 grid(256 / 128, (n + 127) / 128);
            gemm_tf32<true><<<grid, 128, GEMM_SMEM>>>(p_aout, p_Wl, bl, p_hattn, n, 256);
        }
        {
            dim3 grid(1024 / 128, (n + 127) / 128);
            gemm_tf32<false><<<grid, 128, GEMM_SMEM>>>(p_hattn, p_Uc, p_bU, p_hu, n, 1024);
        }
        gate_kernel<<<(n + 3) / 4, 256>>>(outH, outC, s0, cs, n);
    }
}

// round 5
// speedup vs baseline: 4.2376x; 1.1392x over previous
#include <cuda_runtime.h>
#include <math.h>
#include <stdint.h>

#define LEVELS 9
#define N_NODES 87381          // (4^9-1)/3
#define N_INTERNAL 21845
#define LEAF_START 21845
#define LEAF_N 65536

// ---------------- scratch (device globals: allocation-free rule) ----------------
__device__ float g_xT[(size_t)N_NODES * 256];        // tf32-rounded x
__device__ float g_hT[(size_t)N_NODES * 256];        // tf32-rounded h
__device__ float g_xioufq[(size_t)N_INTERNAL * 1280];// internal [iou(768)|f(256)|q(256)]
__device__ float g_xiou_leaf[(size_t)LEAF_N * 768];  // leaf [iou]
__device__ float g_kv[(size_t)65536 * 512];
__device__ float g_aout[(size_t)16384 * 256];        // tf32-rounded
__device__ float g_hu[(size_t)16384 * 1024];
// packed weights, transposed [N][256], tf32-rounded
__device__ float g_Wcat2T[1280 * 256];               // [iou|f|q]
__device__ float g_bcat2[1280];
__device__ float g_WkvT[512 * 256];
__device__ float g_bkv[512];
__device__ float g_UcatT[1024 * 256];                // [Uiou|Uf] transposed (for Wcomb build)
__device__ float g_WlR[256 * 256];                   // Wl row-major, rounded
__device__ float g_WcombRaw[256 * 1024];             // Wl@U  (row-major [k][n])
__device__ float g_WcombT[1024 * 256];               // transposed+rounded
__device__ float g_bcomb[1024];                      // bl@U + bU (fp32)
__device__ float g_zero[1280];                       // stays zero

__device__ __forceinline__ float sigmoidf_(float x) { return 1.0f / (1.0f + expf(-x)); }

__device__ __forceinline__ uint32_t f2tf32(float v) {
    uint32_t r;
    asm("cvt.rna.tf32.f32 %0, %1;" : "=r"(r) : "f"(v));
    return r;
}
__device__ __forceinline__ float roundtf(float v) { return __uint_as_float(f2tf32(v)); }

__device__ __forceinline__ void mma_tf32(float c[4],
                                         uint32_t a0, uint32_t a1, uint32_t a2, uint32_t a3,
                                         uint32_t b0, uint32_t b1) {
    asm volatile("mma.sync.aligned.m16n8k8.row.col.f32.tf32.tf32.f32 "
                 "{%0,%1,%2,%3}, {%4,%5,%6,%7}, {%8,%9}, {%0,%1,%2,%3};\n"
                 : "+f"(c[0]), "+f"(c[1]), "+f"(c[2]), "+f"(c[3])
                 : "r"(a0), "r"(a1), "r"(a2), "r"(a3), "r"(b0), "r"(b1));
}

__device__ __forceinline__ void ldsm_x4(uint32_t& r0, uint32_t& r1, uint32_t& r2, uint32_t& r3,
                                        uint32_t addr) {
    asm volatile("ldmatrix.sync.aligned.m8n8.x4.shared.b16 {%0,%1,%2,%3}, [%4];"
                 : "=r"(r0), "=r"(r1), "=r"(r2), "=r"(r3) : "r"(addr));
}

// ---------------- weight packing ----------------
__global__ void pack_weights(const float* __restrict__ W_iou, const float* __restrict__ b_iou,
                             const float* __restrict__ W_f,   const float* __restrict__ b_f,
                             const float* __restrict__ Wq,    const float* __restrict__ bq,
                             const float* __restrict__ Wk,    const float* __restrict__ bk,
                             const float* __restrict__ Wv,    const float* __restrict__ bv,
                             const float* __restrict__ Wl,
                             const float* __restrict__ Uiou_w,
                             const float* __restrict__ Uf_w)
{
    int idx = blockIdx.x * blockDim.x + threadIdx.x;
    if (idx >= 256 * 1280) return;
    int r = idx / 1280, c = idx % 1280;   // r = k row, c = output col
    float w2;
    if (c < 768)       w2 = W_iou[r * 768 + c];
    else if (c < 1024) w2 = W_f[r * 256 + (c - 768)];
    else               w2 = Wq[r * 256 + (c - 1024)];
    g_Wcat2T[c * 256 + r] = roundtf(w2);
    if (c < 1024) {
        float wu = (c < 768) ? Uiou_w[r * 768 + c] : Uf_w[r * 256 + (c - 768)];
        g_UcatT[c * 256 + r] = roundtf(wu);
    }
    if (c < 512) {
        float wk = (c < 256) ? Wk[r * 256 + c] : Wv[r * 256 + (c - 256)];
        g_WkvT[c * 256 + r] = roundtf(wk);
    }
    if (c < 256) g_WlR[r * 256 + c] = roundtf(Wl[r * 256 + c]);
    if (r == 0) {
        if (c < 768)       g_bcat2[c] = b_iou[c];
        else if (c < 1024) g_bcat2[c] = b_f[c - 768];
        else               g_bcat2[c] = bq[c - 1024];
        if (c < 512) g_bkv[c] = (c < 256) ? bk[c] : bv[c - 256];
    }
}

// transpose+round Wcomb, and build bcomb = bl@U + bU (fp32 from originals)
__global__ void finish_comb(const float* __restrict__ bl,
                            const float* __restrict__ Uiou_w, const float* __restrict__ Uiou_b,
                            const float* __restrict__ Uf_w,   const float* __restrict__ Uf_b)
{
    int idx = blockIdx.x * blockDim.x + threadIdx.x;
    if (idx >= 256 * 1024) return;
    int k = idx >> 10, n = idx & 1023;
    g_WcombT[n * 256 + k] = roundtf(g_WcombRaw[k * 1024 + n]);
    if (k == 0) {
        float s = (n < 768) ? Uiou_b[n] : Uf_b[n - 768];
        for (int j = 0; j < 256; j++) {
            float u = (n < 768) ? Uiou_w[j * 768 + n] : Uf_w[j * 256 + (n - 768)];
            s += bl[j] * u;
        }
        g_bcomb[n] = s;
    }
}

// ---------------- x -> tf32-rounded copy ----------------
__global__ void round_x_kernel(const float* __restrict__ x)
{
    size_t i = (size_t)blockIdx.x * blockDim.x + threadIdx.x;
    if (i >= (size_t)N_NODES * 64) return;   // float4 count
    float4 v = reinterpret_cast<const float4*>(x)[i];
    v.x = roundtf(v.x); v.y = roundtf(v.y); v.z = roundtf(v.z); v.w = roundtf(v.w);
    reinterpret_cast<float4*>(g_xT)[i] = v;
}

// ---------------- TF32 tensor-core GEMM, cp.async 3-stage pipeline ----------------
// C[M,N] = A[M,256] @ Bt[N,256]^T + bias[N].  N % 128 == 0. A,Bt pre-rounded tf32.
#define STAGES 3
#define SROW 36
#define STG_WORDS (2 * 128 * SROW)
#define STG_BYTES (STG_WORDS * 4)
#define GEMM_SMEM (STAGES * STG_BYTES)    // 110592

__device__ __forceinline__ void issue_load(uint32_t sbase, int st,
                                           const float* __restrict__ A,
                                           const float* __restrict__ Bt,
                                           int row0, int col0, int M, int k0,
                                           int rwb, int kq)
{
    uint32_t so = sbase + st * STG_BYTES;
    #pragma unroll
    for (int i = 0; i < 8; i++) {
        int rwi = rwb + 16 * i;
        bool ok = (row0 + rwi) < M;
        uint32_t da = so + (rwi * SROW + kq) * 4;
        const float* ga = A + (size_t)(ok ? (row0 + rwi) : 0) * 256 + k0 + kq;
        int sz = ok ? 16 : 0;
        asm volatile("cp.async.cg.shared.global [%0], [%1], 16, %2;"
                     :: "r"(da), "l"(ga), "r"(sz) : "memory");
        uint32_t db = so + ((128 + rwi) * SROW + kq) * 4;
        const float* gb = Bt + (size_t)(col0 + rwi) * 256 + k0 + kq;
        asm volatile("cp.async.cg.shared.global [%0], [%1], 16;"
                     :: "r"(db), "l"(gb) : "memory");
    }
}

__device__ __forceinline__ void compute_stage(uint32_t soff,
                                              const uint32_t aoff[4], const uint32_t boff[4],
                                              float acc[4][8][4])
{
    #pragma unroll
    for (int kk = 0; kk < 32; kk += 8) {
        uint32_t af[4][4];
        #pragma unroll
        for (int mi = 0; mi < 4; mi++)
            ldsm_x4(af[mi][0], af[mi][1], af[mi][2], af[mi][3], soff + aoff[mi] + kk * 4);
        uint32_t bf[8][2];
        #pragma unroll
        for (int np = 0; np < 4; np++)
            ldsm_x4(bf[2 * np][0], bf[2 * np][1], bf[2 * np + 1][0], bf[2 * np + 1][1],
                    soff + boff[np] + kk * 4);
        #pragma unroll
        for (int mi = 0; mi < 4; mi++)
            #pragma unroll
            for (int ni = 0; ni < 8; ni++)
                mma_tf32(acc[mi][ni],
                         af[mi][0], af[mi][1], af[mi][2], af[mi][3],
                         bf[ni][0], bf[ni][1]);
    }
}

__global__ void __launch_bounds__(128) gemm_tf32(const float* __restrict__ A,
                                                 const float* __restrict__ Bt,
                                                 const float* __restrict__ bias,
                                                 float* __restrict__ C, int M, int N)
{
    extern __shared__ uint32_t sm[];
    int tid  = threadIdx.x;
    int lane = tid & 31;
    int warp = tid >> 5;
    int wr = warp >> 1, wc = warp & 1;
    int g  = lane >> 3, r8 = lane & 7;
    int gid = lane >> 2, tig = lane & 3;
    int row0 = blockIdx.y * 128;
    int col0 = blockIdx.x * 128;
    int rwb = tid >> 3, kq = (tid & 7) << 2;

    uint32_t sbase = (uint32_t)__cvta_generic_to_shared(sm);
    uint32_t aoff[4], boff[4];
    #pragma unroll
    for (int mi = 0; mi < 4; mi++) {
        int row = wr * 64 + mi * 16 + ((g & 1) << 3) + r8;
        aoff[mi] = (row * SROW + ((g >> 1) << 2)) * 4;
    }
    #pragma unroll
    for (int np = 0; np < 4; np++) {
        int row = 128 + wc * 64 + np * 16 + ((g >> 1) << 3) + r8;
        boff[np] = (row * SROW + ((g & 1) << 2)) * 4;
    }

    float acc[4][8][4];
    #pragma unroll
    for (int mi = 0; mi < 4; mi++)
        #pragma unroll
        for (int ni = 0; ni < 8; ni++)
            #pragma unroll
            for (int t = 0; t < 4; t++) acc[mi][ni][t] = 0.0f;

    issue_load(sbase, 0, A, Bt, row0, col0, M, 0, rwb, kq);
    asm volatile("cp.async.commit_group;" ::: "memory");
    issue_load(sbase, 1, A, Bt, row0, col0, M, 32, rwb, kq);
    asm volatile("cp.async.commit_group;" ::: "memory");

    #pragma unroll
    for (int it = 0; it < 8; it++) {
        asm volatile("cp.async.wait_group 1;" ::: "memory");
        __syncthreads();
        compute_stage(sbase + (it % 3) * STG_BYTES, aoff, boff, acc);
        if (it + 2 < 8)
            issue_load(sbase, (it + 2) % 3, A, Bt, row0, col0, M, (it + 2) * 32, rwb, kq);
        asm volatile("cp.async.commit_group;" ::: "memory");
    }

    #pragma unroll
    for (int mi = 0; mi < 4; mi++) {
        int rbase = row0 + wr * 64 + mi * 16 + gid;
        #pragma unroll
        for (int ni = 0; ni < 8; ni++) {
            int c = col0 + wc * 64 + ni * 8 + 2 * tig;
            float b0 = bias[c], b1 = bias[c + 1];
            if (rbase < M) {
                float v0 = acc[mi][ni][0] + b0, v1 = acc[mi][ni][1] + b1;
                *reinterpret_cast<float2*>(C + (size_t)rbase * N + c) = make_float2(v0, v1);
            }
            if (rbase + 8 < M) {
                float v2 = acc[mi][ni][2] + b0, v3 = acc[mi][ni][3] + b1;
                *reinterpret_cast<float2*>(C + (size_t)(rbase + 8) * N + c) = make_float2(v2, v3);
            }
        }
    }
}

// ---------------- leaf level: gates from g_xiou_leaf (stride 768), float4 ----------------
__global__ void leaf_kernel(float* __restrict__ outH, float* __restrict__ outC)
{
    int t  = threadIdx.x;
    int jj = blockIdx.x * 4 + (t >> 6);
    int d  = (t & 63) * 4;
    const float* r = g_xiou_leaf + (size_t)jj * 768;
    float4 iv = *reinterpret_cast<const float4*>(r + d);
    float4 ov = *reinterpret_cast<const float4*>(r + 256 + d);
    float4 uv = *reinterpret_cast<const float4*>(r + 512 + d);
    float4 c4, h4, hr4;
    #pragma unroll
    for (int q = 0; q < 4; q++) {
        float i = (&iv.x)[q], o = (&ov.x)[q], u = (&uv.x)[q];
        float c = sigmoidf_(i) * tanhf(u);
        float h = sigmoidf_(o) * tanhf(c);
        (&c4.x)[q] = c; (&h4.x)[q] = h; (&hr4.x)[q] = roundtf(h);
    }
    size_t base = (size_t)(LEAF_START + jj) * 256 + d;
    *reinterpret_cast<float4*>(outH + base) = h4;
    *reinterpret_cast<float4*>(outC + base) = c4;
    *reinterpret_cast<float4*>(g_hT + base) = hr4;
}

// ---------------- attention: warp per (node, head), q from g_xioufq ----------------
__global__ void attn_kernel(int s0)
{
    int j = blockIdx.x;               // level-local node
    int node = s0 + j;                // global internal node (= row in g_xioufq)
    int w = threadIdx.x >> 5;
    int t = threadIdx.x & 31;
    const float scale = 0.17677669529663687f; // 1/sqrt(32)
    float qv = g_xioufq[(size_t)node * 1280 + 1024 + w * 32 + t];
    float logit[4];
    #pragma unroll
    for (int k = 0; k < 4; k++) {
        float kk = g_kv[(size_t)(4 * j + k) * 512 + w * 32 + t];
        float p = qv * kk;
        #pragma unroll
        for (int off = 16; off; off >>= 1) p += __shfl_xor_sync(0xffffffffu, p, off);
        logit[k] = p * scale;
    }
    float m = fmaxf(fmaxf(logit[0], logit[1]), fmaxf(logit[2], logit[3]));
    float e[4], s = 0.f;
    #pragma unroll
    for (int k = 0; k < 4; k++) { e[k] = expf(logit[k] - m); s += e[k]; }
    float inv = 1.0f / s;
    float o = 0.f;
    #pragma unroll
    for (int k = 0; k < 4; k++)
        o += e[k] * inv * g_kv[(size_t)(4 * j + k) * 512 + 256 + w * 32 + t];
    g_aout[(size_t)j * 256 + w * 32 + t] = roundtf(o);
}

// ---------------- internal-level gates, float4 ----------------
__global__ void gate_kernel(float* __restrict__ outH, float* __restrict__ outC,
                            int s0, int cs, int n)
{
    int t  = threadIdx.x;
    int jj = blockIdx.x * 4 + (t >> 6);
    if (jj >= n) return;
    int d  = (t & 63) * 4;
    int node = s0 + jj;
    const float* xr = g_xioufq + (size_t)node * 1280;
    const float* hr = g_hu + (size_t)jj * 1024;
    float4 i4 = *reinterpret_cast<const float4*>(xr + d);
    float4 o4 = *reinterpret_cast<const float4*>(xr + 256 + d);
    float4 u4 = *reinterpret_cast<const float4*>(xr + 512 + d);
    float4 f4 = *reinterpret_cast<const float4*>(xr + 768 + d);
    float4 hi = *reinterpret_cast<const float4*>(hr + d);
    float4 ho = *reinterpret_cast<const float4*>(hr + 256 + d);
    float4 hu4 = *reinterpret_cast<const float4*>(hr + 512 + d);
    float4 hf = *reinterpret_cast<const float4*>(hr + 768 + d);
    float4 cs4 = make_float4(0.f, 0.f, 0.f, 0.f);
    #pragma unroll
    for (int k = 0; k < 4; k++) {
        float4 cc = *reinterpret_cast<const float4*>(outC + (size_t)(cs + 4 * jj + k) * 256 + d);
        cs4.x += cc.x; cs4.y += cc.y; cs4.z += cc.z; cs4.w += cc.w;
    }
    float4 c4, h4, hr4;
    #pragma unroll
    for (int q = 0; q < 4; q++) {
        float i = (&i4.x)[q] + (&hi.x)[q];
        float o = (&o4.x)[q] + (&ho.x)[q];
        float u = (&u4.x)[q] + (&hu4.x)[q];
        float f = sigmoidf_((&f4.x)[q] + (&hf.x)[q]);
        float c = sigmoidf_(i) * tanhf(u) + f * (&cs4.x)[q];
        float h = sigmoidf_(o) * tanhf(c);
        (&c4.x)[q] = c; (&h4.x)[q] = h; (&hr4.x)[q] = roundtf(h);
    }
    size_t base = (size_t)node * 256 + d;
    *reinterpret_cast<float4*>(outH + base) = h4;
    *reinterpret_cast<float4*>(outC + base) = c4;
    *reinterpret_cast<float4*>(g_hT + base) = hr4;
}

// ---------------- host launch ----------------
extern "C" void kernel_launch(void* const* d_in, const int* in_sizes, int n_in,
                              void* d_out, int out_size)
{
    const float* x      = (const float*)d_in[0];
    const float* W_iou  = (const float*)d_in[1];
    const float* b_iou  = (const float*)d_in[2];
    const float* W_f    = (const float*)d_in[3];
    const float* b_f    = (const float*)d_in[4];
    const float* Wq     = (const float*)d_in[5];
    const float* bq     = (const float*)d_in[6];
    const float* Wk     = (const float*)d_in[7];
    const float* bk     = (const float*)d_in[8];
    const float* Wv     = (const float*)d_in[9];
    const float* bv     = (const float*)d_in[10];
    const float* Wl     = (const float*)d_in[11];
    const float* bl     = (const float*)d_in[12];
    const float* Uiou_w = (const float*)d_in[13];
    const float* Uiou_b = (const float*)d_in[14];
    const float* Uf_w   = (const float*)d_in[15];
    const float* Uf_b   = (const float*)d_in[16];

    float* outH = (float*)d_out;
    float* outC = outH + (size_t)N_NODES * 256;

    static bool attr_set = false;
    if (!attr_set) {
        cudaFuncSetAttribute(gemm_tf32, cudaFuncAttributeMaxDynamicSharedMemorySize, GEMM_SMEM);
        attr_set = true;
    }

    float *p_xT, *p_hT, *p_xioufq, *p_xleaf, *p_kv, *p_aout, *p_hu;
    float *p_W2, *p_b2, *p_Wkv, *p_bkv, *p_Uc, *p_WlR, *p_WcR, *p_WcT, *p_bc, *p_zero;
    cudaGetSymbolAddress((void**)&p_xT,     g_xT);
    cudaGetSymbolAddress((void**)&p_hT,     g_hT);
    cudaGetSymbolAddress((void**)&p_xioufq, g_xioufq);
    cudaGetSymbolAddress((void**)&p_xleaf,  g_xiou_leaf);
    cudaGetSymbolAddress((void**)&p_kv,     g_kv);
    cudaGetSymbolAddress((void**)&p_aout,   g_aout);
    cudaGetSymbolAddress((void**)&p_hu,     g_hu);
    cudaGetSymbolAddress((void**)&p_W2,     g_Wcat2T);
    cudaGetSymbolAddress((void**)&p_b2,     g_bcat2);
    cudaGetSymbolAddress((void**)&p_Wkv,    g_WkvT);
    cudaGetSymbolAddress((void**)&p_bkv,    g_bkv);
    cudaGetSymbolAddress((void**)&p_Uc,     g_UcatT);
    cudaGetSymbolAddress((void**)&p_WlR,    g_WlR);
    cudaGetSymbolAddress((void**)&p_WcR,    g_WcombRaw);
    cudaGetSymbolAddress((void**)&p_WcT,    g_WcombT);
    cudaGetSymbolAddress((void**)&p_bc,     g_bcomb);
    cudaGetSymbolAddress((void**)&p_zero,   g_zero);

    static const int starts[LEVELS + 1] =
        {0, 1, 5, 21, 85, 341, 1365, 5461, 21845, 87381};

    pack_weights<<<(256 * 1280 + 255) / 256, 256>>>(
        W_iou, b_iou, W_f, b_f, Wq, bq, Wk, bk, Wv, bv, Wl, Uiou_w, Uf_w);

    // Wcomb = WlR @ UcatT^T  (256x1024), then transpose+round and build bcomb
    {
        dim3 grid(1024 / 128, 2);
        gemm_tf32<<<grid, 128, GEMM_SMEM>>>(p_WlR, p_Uc, p_zero, p_WcR, 256, 1024);
    }
    finish_comb<<<(256 * 1024 + 255) / 256, 256>>>(bl, Uiou_w, Uiou_b, Uf_w, Uf_b);

    round_x_kernel<<<(N_NODES * 64 + 255) / 256, 256>>>(x);

    // leaf iou (N=768) and internal iou|f|q (N=1280)
    {
        dim3 grid(768 / 128, LEAF_N / 128);
        gemm_tf32<<<grid, 128, GEMM_SMEM>>>(p_xT + (size_t)LEAF_START * 256,
                                            p_W2, p_b2, p_xleaf, LEAF_N, 768);
    }
    leaf_kernel<<<LEAF_N / 4, 256>>>(outH, outC);
    {
        dim3 grid(1280 / 128, (N_INTERNAL + 127) / 128);
        gemm_tf32<<<grid, 128, GEMM_SMEM>>>(p_xT, p_W2, p_b2, p_xioufq, N_INTERNAL, 1280);
    }

    for (int l = LEVELS - 2; l >= 0; --l) {
        int n  = 1 << (2 * l);
        int s0 = starts[l];
        int cs = starts[l + 1];
        int nc = 4 * n;

        {
            dim3 grid(512 / 128, (nc + 127) / 128);
            gemm_tf32<<<grid, 128, GEMM_SMEM>>>(p_hT + (size_t)cs * 256,
                                                p_Wkv, p_bkv, p_kv, nc, 512);
        }
        attn_kernel<<<n, 256>>>(s0);
        {
            dim3 grid(1024 / 128, (n + 127) / 128);
            gemm_tf32<<<grid, 128, GEMM_SMEM>>>(p_aout, p_WcT, p_bc, p_hu, n, 1024);
        }
        gate_kernel<<<(n + 3) / 4, 256>>>(outH, outC, s0, cs, n);
    }
}

// round 6
// speedup vs baseline: 5.7124x; 1.3480x over previous
#include <cuda_runtime.h>
#include <cuda_fp16.h>
#include <math.h>
#include <stdint.h>

#define LEVELS 9
#define N_NODES 87381          // (4^9-1)/3
#define N_INTERNAL 21845
#define LEAF_START 21845
#define LEAF_N 65536

// ---------------- scratch (device globals: allocation-free rule) ----------------
__device__ __half g_xH[(size_t)N_NODES * 256];        // fp16 x
__device__ __half g_hH[(size_t)N_NODES * 256];        // fp16 h
__device__ float  g_xioufq[(size_t)N_INTERNAL * 1280];// internal [iou(768)|f(256)|q(256)]
__device__ float  g_xiou_leaf[(size_t)LEAF_N * 768];  // leaf [iou]
__device__ float  g_kv[(size_t)65536 * 512];
__device__ __half g_aoutH[(size_t)16384 * 256];       // fp16 attention out
__device__ float  g_hu[(size_t)16384 * 1024];
// packed weights, transposed [N][256], fp16
__device__ __half g_Wcat2T[1280 * 256];               // [iou|f|q]
__device__ float  g_bcat2[1280];
__device__ __half g_WkvT[512 * 256];
__device__ float  g_bkv[512];
__device__ __half g_UcatT[1024 * 256];                // [Uiou|Uf] transposed
__device__ __half g_WlR[256 * 256];                   // Wl row-major fp16
__device__ float  g_WcombRaw[256 * 1024];             // Wl@U fp32 [k][n]
__device__ __half g_WcombT[1024 * 256];               // transposed fp16
__device__ float  g_bcomb[1024];                      // bl@U + bU (fp32)
__device__ float  g_zero[1280];                       // stays zero

__device__ __forceinline__ float sigmoidf_(float x) { return 1.0f / (1.0f + expf(-x)); }

__device__ __forceinline__ void mma_fp16(float c[4],
                                         uint32_t a0, uint32_t a1, uint32_t a2, uint32_t a3,
                                         uint32_t b0, uint32_t b1) {
    asm volatile("mma.sync.aligned.m16n8k16.row.col.f32.f16.f16.f32 "
                 "{%0,%1,%2,%3}, {%4,%5,%6,%7}, {%8,%9}, {%0,%1,%2,%3};\n"
                 : "+f"(c[0]), "+f"(c[1]), "+f"(c[2]), "+f"(c[3])
                 : "r"(a0), "r"(a1), "r"(a2), "r"(a3), "r"(b0), "r"(b1));
}

__device__ __forceinline__ void ldsm_x4(uint32_t& r0, uint32_t& r1, uint32_t& r2, uint32_t& r3,
                                        uint32_t addr) {
    asm volatile("ldmatrix.sync.aligned.m8n8.x4.shared.b16 {%0,%1,%2,%3}, [%4];"
                 : "=r"(r0), "=r"(r1), "=r"(r2), "=r"(r3) : "r"(addr));
}

// ---------------- weight packing ----------------
__global__ void pack_weights(const float* __restrict__ W_iou, const float* __restrict__ b_iou,
                             const float* __restrict__ W_f,   const float* __restrict__ b_f,
                             const float* __restrict__ Wq,    const float* __restrict__ bq,
                             const float* __restrict__ Wk,    const float* __restrict__ bk,
                             const float* __restrict__ Wv,    const float* __restrict__ bv,
                             const float* __restrict__ Wl,
                             const float* __restrict__ Uiou_w,
                             const float* __restrict__ Uf_w)
{
    int idx = blockIdx.x * blockDim.x + threadIdx.x;
    if (idx >= 256 * 1280) return;
    int r = idx / 1280, c = idx % 1280;   // r = k row, c = output col
    float w2;
    if (c < 768)       w2 = W_iou[r * 768 + c];
    else if (c < 1024) w2 = W_f[r * 256 + (c - 768)];
    else               w2 = Wq[r * 256 + (c - 1024)];
    g_Wcat2T[c * 256 + r] = __float2half(w2);
    if (c < 1024) {
        float wu = (c < 768) ? Uiou_w[r * 768 + c] : Uf_w[r * 256 + (c - 768)];
        g_UcatT[c * 256 + r] = __float2half(wu);
    }
    if (c < 512) {
        float wk = (c < 256) ? Wk[r * 256 + c] : Wv[r * 256 + (c - 256)];
        g_WkvT[c * 256 + r] = __float2half(wk);
    }
    if (c < 256) g_WlR[r * 256 + c] = __float2half(Wl[r * 256 + c]);
    if (r == 0) {
        if (c < 768)       g_bcat2[c] = b_iou[c];
        else if (c < 1024) g_bcat2[c] = b_f[c - 768];
        else               g_bcat2[c] = bq[c - 1024];
        if (c < 512) g_bkv[c] = (c < 256) ? bk[c] : bv[c - 256];
    }
}

// transpose+convert Wcomb, and build bcomb = bl@U + bU (fp32 from originals)
__global__ void finish_comb(const float* __restrict__ bl,
                            const float* __restrict__ Uiou_w, const float* __restrict__ Uiou_b,
                            const float* __restrict__ Uf_w,   const float* __restrict__ Uf_b)
{
    int idx = blockIdx.x * blockDim.x + threadIdx.x;
    if (idx >= 256 * 1024) return;
    int k = idx >> 10, n = idx & 1023;
    g_WcombT[n * 256 + k] = __float2half(g_WcombRaw[k * 1024 + n]);
    if (k == 0) {
        float s = (n < 768) ? Uiou_b[n] : Uf_b[n - 768];
        for (int j = 0; j < 256; j++) {
            float u = (n < 768) ? Uiou_w[j * 768 + n] : Uf_w[j * 256 + (n - 768)];
            s += bl[j] * u;
        }
        g_bcomb[n] = s;
    }
}

// ---------------- x -> fp16 convert ----------------
__global__ void convert_x_kernel(const float* __restrict__ x)
{
    size_t i = (size_t)blockIdx.x * blockDim.x + threadIdx.x;
    if (i >= (size_t)N_NODES * 64) return;   // float4 count
    float4 v = reinterpret_cast<const float4*>(x)[i];
    __half2 h0 = __floats2half2_rn(v.x, v.y);
    __half2 h1 = __floats2half2_rn(v.z, v.w);
    uint2 pack;
    pack.x = *reinterpret_cast<uint32_t*>(&h0);
    pack.y = *reinterpret_cast<uint32_t*>(&h1);
    reinterpret_cast<uint2*>(g_xH)[i] = pack;
}

// ---------------- FP16 tensor-core GEMM, cp.async 3-stage pipeline ----------------
// C[M,N] = A[M,256] @ Bt[N,256]^T + bias[N].  N % 128 == 0.  A,Bt fp16.
#define STAGES 3
#define SROWH 40                          // 32 k-halves + 8 pad
#define STGH_BYTES (256 * SROWH * 2)      // A(128) + B(128) rows = 20480
#define GEMM_SMEM (STAGES * STGH_BYTES)   // 61440

__device__ __forceinline__ void issue_load(uint32_t sbase, int st,
                                           const __half* __restrict__ A,
                                           const __half* __restrict__ Bt,
                                           int row0, int col0, int M, int k0, int tid)
{
    uint32_t so = sbase + st * STGH_BYTES;
    int row4 = tid >> 2;          // 0..31
    int ch   = (tid & 3) * 8;     // half offset within 32-half row chunk
    #pragma unroll
    for (int i = 0; i < 4; i++) {
        int r = row4 + 32 * i;
        bool ok = (row0 + r) < M;
        uint32_t da = so + (r * SROWH + ch) * 2;
        const __half* ga = A + (size_t)(ok ? (row0 + r) : 0) * 256 + k0 + ch;
        int sz = ok ? 16 : 0;
        asm volatile("cp.async.cg.shared.global [%0], [%1], 16, %2;"
                     :: "r"(da), "l"(ga), "r"(sz) : "memory");
        uint32_t db = so + ((128 + r) * SROWH + ch) * 2;
        const __half* gb = Bt + (size_t)(col0 + r) * 256 + k0 + ch;
        asm volatile("cp.async.cg.shared.global [%0], [%1], 16;"
                     :: "r"(db), "l"(gb) : "memory");
    }
}

__device__ __forceinline__ void compute_stage(uint32_t soff,
                                              const uint32_t aoff[4], const uint32_t boff[4],
                                              float acc[4][8][4])
{
    #pragma unroll
    for (int kk = 0; kk < 32; kk += 16) {
        uint32_t af[4][4];
        #pragma unroll
        for (int mi = 0; mi < 4; mi++)
            ldsm_x4(af[mi][0], af[mi][1], af[mi][2], af[mi][3], soff + aoff[mi] + kk * 2);
        uint32_t bf[8][2];
        #pragma unroll
        for (int np = 0; np < 4; np++)
            ldsm_x4(bf[2 * np][0], bf[2 * np][1], bf[2 * np + 1][0], bf[2 * np + 1][1],
                    soff + boff[np] + kk * 2);
        #pragma unroll
        for (int mi = 0; mi < 4; mi++)
            #pragma unroll
            for (int ni = 0; ni < 8; ni++)
                mma_fp16(acc[mi][ni],
                         af[mi][0], af[mi][1], af[mi][2], af[mi][3],
                         bf[ni][0], bf[ni][1]);
    }
}

__global__ void __launch_bounds__(128) gemm_fp16(const __half* __restrict__ A,
                                                 const __half* __restrict__ Bt,
                                                 const float* __restrict__ bias,
                                                 float* __restrict__ C, int M, int N)
{
    extern __shared__ uint32_t sm[];
    int tid  = threadIdx.x;
    int lane = tid & 31;
    int warp = tid >> 5;
    int wr = warp >> 1, wc = warp & 1;
    int g  = lane >> 3, r8 = lane & 7;
    int gid = lane >> 2, tig = lane & 3;
    int row0 = blockIdx.y * 128;
    int col0 = blockIdx.x * 128;

    uint32_t sbase = (uint32_t)__cvta_generic_to_shared(sm);
    // A frag tiles {a0..a3} = (m0-7,k0-7),(m8-15,k0-7),(m0-7,k8-15),(m8-15,k8-15)
    uint32_t aoff[4], boff[4];
    #pragma unroll
    for (int mi = 0; mi < 4; mi++) {
        int row = wr * 64 + mi * 16 + ((g & 1) << 3) + r8;
        aoff[mi] = (row * SROWH + ((g >> 1) << 3)) * 2;
    }
    // B frag pairs: tiles (n0-7,k0-7),(n0-7,k8-15),(n8-15,k0-7),(n8-15,k8-15)
    #pragma unroll
    for (int np = 0; np < 4; np++) {
        int row = 128 + wc * 64 + np * 16 + ((g >> 1) << 3) + r8;
        boff[np] = (row * SROWH + ((g & 1) << 3)) * 2;
    }

    float acc[4][8][4];
    #pragma unroll
    for (int mi = 0; mi < 4; mi++)
        #pragma unroll
        for (int ni = 0; ni < 8; ni++)
            #pragma unroll
            for (int t = 0; t < 4; t++) acc[mi][ni][t] = 0.0f;

    issue_load(sbase, 0, A, Bt, row0, col0, M, 0, tid);
    asm volatile("cp.async.commit_group;" ::: "memory");
    issue_load(sbase, 1, A, Bt, row0, col0, M, 32, tid);
    asm volatile("cp.async.commit_group;" ::: "memory");

    #pragma unroll
    for (int it = 0; it < 8; it++) {
        asm volatile("cp.async.wait_group 1;" ::: "memory");
        __syncthreads();
        compute_stage(sbase + (it % 3) * STGH_BYTES, aoff, boff, acc);
        if (it + 2 < 8)
            issue_load(sbase, (it + 2) % 3, A, Bt, row0, col0, M, (it + 2) * 32, tid);
        asm volatile("cp.async.commit_group;" ::: "memory");
    }

    #pragma unroll
    for (int mi = 0; mi < 4; mi++) {
        int rbase = row0 + wr * 64 + mi * 16 + gid;
        #pragma unroll
        for (int ni = 0; ni < 8; ni++) {
            int c = col0 + wc * 64 + ni * 8 + 2 * tig;
            float b0 = bias[c], b1 = bias[c + 1];
            if (rbase < M) {
                float v0 = acc[mi][ni][0] + b0, v1 = acc[mi][ni][1] + b1;
                *reinterpret_cast<float2*>(C + (size_t)rbase * N + c) = make_float2(v0, v1);
            }
            if (rbase + 8 < M) {
                float v2 = acc[mi][ni][2] + b0, v3 = acc[mi][ni][3] + b1;
                *reinterpret_cast<float2*>(C + (size_t)(rbase + 8) * N + c) = make_float2(v2, v3);
            }
        }
    }
}

// ---------------- leaf level: gates from g_xiou_leaf (stride 768), float4 ----------------
__global__ void leaf_kernel(float* __restrict__ outH, float* __restrict__ outC)
{
    int t  = threadIdx.x;
    int jj = blockIdx.x * 4 + (t >> 6);
    int d  = (t & 63) * 4;
    const float* r = g_xiou_leaf + (size_t)jj * 768;
    float4 iv = *reinterpret_cast<const float4*>(r + d);
    float4 ov = *reinterpret_cast<const float4*>(r + 256 + d);
    float4 uv = *reinterpret_cast<const float4*>(r + 512 + d);
    float4 c4, h4;
    __half hh[4];
    #pragma unroll
    for (int q = 0; q < 4; q++) {
        float i = (&iv.x)[q], o = (&ov.x)[q], u = (&uv.x)[q];
        float c = sigmoidf_(i) * tanhf(u);
        float h = sigmoidf_(o) * tanhf(c);
        (&c4.x)[q] = c; (&h4.x)[q] = h; hh[q] = __float2half(h);
    }
    size_t base = (size_t)(LEAF_START + jj) * 256 + d;
    *reinterpret_cast<float4*>(outH + base) = h4;
    *reinterpret_cast<float4*>(outC + base) = c4;
    *reinterpret_cast<uint2*>(g_hH + base) = *reinterpret_cast<uint2*>(hh);
}

// ---------------- attention: warp per (node, head), q from g_xioufq ----------------
__global__ void attn_kernel(int s0)
{
    int j = blockIdx.x;
    int node = s0 + j;
    int w = threadIdx.x >> 5;
    int t = threadIdx.x & 31;
    const float scale = 0.17677669529663687f; // 1/sqrt(32)
    float qv = g_xioufq[(size_t)node * 1280 + 1024 + w * 32 + t];
    float logit[4];
    #pragma unroll
    for (int k = 0; k < 4; k++) {
        float kk = g_kv[(size_t)(4 * j + k) * 512 + w * 32 + t];
        float p = qv * kk;
        #pragma unroll
        for (int off = 16; off; off >>= 1) p += __shfl_xor_sync(0xffffffffu, p, off);
        logit[k] = p * scale;
    }
    float m = fmaxf(fmaxf(logit[0], logit[1]), fmaxf(logit[2], logit[3]));
    float e[4], s = 0.f;
    #pragma unroll
    for (int k = 0; k < 4; k++) { e[k] = expf(logit[k] - m); s += e[k]; }
    float inv = 1.0f / s;
    float o = 0.f;
    #pragma unroll
    for (int k = 0; k < 4; k++)
        o += e[k] * inv * g_kv[(size_t)(4 * j + k) * 512 + 256 + w * 32 + t];
    g_aoutH[(size_t)j * 256 + w * 32 + t] = __float2half(o);
}

// ---------------- internal-level gates, float4 ----------------
__global__ void gate_kernel(float* __restrict__ outH, float* __restrict__ outC,
                            int s0, int cs, int n)
{
    int t  = threadIdx.x;
    int jj = blockIdx.x * 4 + (t >> 6);
    if (jj >= n) return;
    int d  = (t & 63) * 4;
    int node = s0 + jj;
    const float* xr = g_xioufq + (size_t)node * 1280;
    const float* hr = g_hu + (size_t)jj * 1024;
    float4 i4 = *reinterpret_cast<const float4*>(xr + d);
    float4 o4 = *reinterpret_cast<const float4*>(xr + 256 + d);
    float4 u4 = *reinterpret_cast<const float4*>(xr + 512 + d);
    float4 f4 = *reinterpret_cast<const float4*>(xr + 768 + d);
    float4 hi = *reinterpret_cast<const float4*>(hr + d);
    float4 ho = *reinterpret_cast<const float4*>(hr + 256 + d);
    float4 hu4 = *reinterpret_cast<const float4*>(hr + 512 + d);
    float4 hf = *reinterpret_cast<const float4*>(hr + 768 + d);
    float4 cs4 = make_float4(0.f, 0.f, 0.f, 0.f);
    #pragma unroll
    for (int k = 0; k < 4; k++) {
        float4 cc = *reinterpret_cast<const float4*>(outC + (size_t)(cs + 4 * jj + k) * 256 + d);
        cs4.x += cc.x; cs4.y += cc.y; cs4.z += cc.z; cs4.w += cc.w;
    }
    float4 c4, h4;
    __half hh[4];
    #pragma unroll
    for (int q = 0; q < 4; q++) {
        float i = (&i4.x)[q] + (&hi.x)[q];
        float o = (&o4.x)[q] + (&ho.x)[q];
        float u = (&u4.x)[q] + (&hu4.x)[q];
        float f = sigmoidf_((&f4.x)[q] + (&hf.x)[q]);
        float c = sigmoidf_(i) * tanhf(u) + f * (&cs4.x)[q];
        float h = sigmoidf_(o) * tanhf(c);
        (&c4.x)[q] = c; (&h4.x)[q] = h; hh[q] = __float2half(h);
    }
    size_t base = (size_t)node * 256 + d;
    *reinterpret_cast<float4*>(outH + base) = h4;
    *reinterpret_cast<float4*>(outC + base) = c4;
    *reinterpret_cast<uint2*>(g_hH + base) = *reinterpret_cast<uint2*>(hh);
}

// ---------------- host launch ----------------
extern "C" void kernel_launch(void* const* d_in, const int* in_sizes, int n_in,
                              void* d_out, int out_size)
{
    const float* x      = (const float*)d_in[0];
    const float* W_iou  = (const float*)d_in[1];
    const float* b_iou  = (const float*)d_in[2];
    const float* W_f    = (const float*)d_in[3];
    const float* b_f    = (const float*)d_in[4];
    const float* Wq     = (const float*)d_in[5];
    const float* bq     = (const float*)d_in[6];
    const float* Wk     = (const float*)d_in[7];
    const float* bk     = (const float*)d_in[8];
    const float* Wv     = (const float*)d_in[9];
    const float* bv     = (const float*)d_in[10];
    const float* Wl     = (const float*)d_in[11];
    const float* bl     = (const float*)d_in[12];
    const float* Uiou_w = (const float*)d_in[13];
    const float* Uiou_b = (const float*)d_in[14];
    const float* Uf_w   = (const float*)d_in[15];
    const float* Uf_b   = (const float*)d_in[16];

    float* outH = (float*)d_out;
    float* outC = outH + (size_t)N_NODES * 256;

    static bool attr_set = false;
    if (!attr_set) {
        cudaFuncSetAttribute(gemm_fp16, cudaFuncAttributeMaxDynamicSharedMemorySize, GEMM_SMEM);
        attr_set = true;
    }

    __half *p_xH, *p_hH, *p_aoutH, *p_W2, *p_Wkv, *p_Uc, *p_WlR, *p_WcT;
    float *p_xioufq, *p_xleaf, *p_kv, *p_hu;
    float *p_b2, *p_bkv, *p_WcR, *p_bc, *p_zero;
    cudaGetSymbolAddress((void**)&p_xH,     g_xH);
    cudaGetSymbolAddress((void**)&p_hH,     g_hH);
    cudaGetSymbolAddress((void**)&p_aoutH,  g_aoutH);
    cudaGetSymbolAddress((void**)&p_xioufq, g_xioufq);
    cudaGetSymbolAddress((void**)&p_xleaf,  g_xiou_leaf);
    cudaGetSymbolAddress((void**)&p_kv,     g_kv);
    cudaGetSymbolAddress((void**)&p_hu,     g_hu);
    cudaGetSymbolAddress((void**)&p_W2,     g_Wcat2T);
    cudaGetSymbolAddress((void**)&p_b2,     g_bcat2);
    cudaGetSymbolAddress((void**)&p_Wkv,    g_WkvT);
    cudaGetSymbolAddress((void**)&p_bkv,    g_bkv);
    cudaGetSymbolAddress((void**)&p_Uc,     g_UcatT);
    cudaGetSymbolAddress((void**)&p_WlR,    g_WlR);
    cudaGetSymbolAddress((void**)&p_WcR,    g_WcombRaw);
    cudaGetSymbolAddress((void**)&p_WcT,    g_WcombT);
    cudaGetSymbolAddress((void**)&p_bc,     g_bcomb);
    cudaGetSymbolAddress((void**)&p_zero,   g_zero);

    static const int starts[LEVELS + 1] =
        {0, 1, 5, 21, 85, 341, 1365, 5461, 21845, 87381};

    pack_weights<<<(256 * 1280 + 255) / 256, 256>>>(
        W_iou, b_iou, W_f, b_f, Wq, bq, Wk, bk, Wv, bv, Wl, Uiou_w, Uf_w);

    // Wcomb = WlR @ UcatT^T (256x1024), then transpose+convert and build bcomb
    {
        dim3 grid(1024 / 128, 2);
        gemm_fp16<<<grid, 128, GEMM_SMEM>>>(p_WlR, p_Uc, p_zero, p_WcR, 256, 1024);
    }
    finish_comb<<<(256 * 1024 + 255) / 256, 256>>>(bl, Uiou_w, Uiou_b, Uf_w, Uf_b);

    convert_x_kernel<<<(N_NODES * 64 + 255) / 256, 256>>>(x);

    // leaf iou (N=768) and internal iou|f|q (N=1280)
    {
        dim3 grid(768 / 128, LEAF_N / 128);
        gemm_fp16<<<grid, 128, GEMM_SMEM>>>(p_xH + (size_t)LEAF_START * 256,
                                            p_W2, p_b2, p_xleaf, LEAF_N, 768);
    }
    leaf_kernel<<<LEAF_N / 4, 256>>>(outH, outC);
    {
        dim3 grid(1280 / 128, (N_INTERNAL + 127) / 128);
        gemm_fp16<<<grid, 128, GEMM_SMEM>>>(p_xH, p_W2, p_b2, p_xioufq, N_INTERNAL, 1280);
    }

    for (int l = LEVELS - 2; l >= 0; --l) {
        int n  = 1 << (2 * l);
        int s0 = starts[l];
        int cs = starts[l + 1];
        int nc = 4 * n;

        {
            dim3 grid(512 / 128, (nc + 127) / 128);
            gemm_fp16<<<grid, 128, GEMM_SMEM>>>(p_hH + (size_t)cs * 256,
                                                p_Wkv, p_bkv, p_kv, nc, 512);
        }
        attn_kernel<<<n, 256>>>(s0);
        {
            dim3 grid(1024 / 128, (n + 127) / 128);
            gemm_fp16<<<grid, 128, GEMM_SMEM>>>(p_aoutH, p_WcT, p_bc, p_hu, n, 1024);
        }
        gate_kernel<<<(n + 3) / 4, 256>>>(outH, outC, s0, cs, n);
    }
}

// round 7
// speedup vs baseline: 6.1791x; 1.0817x over previous
#include <cuda_runtime.h>
#include <cuda_fp16.h>
#include <math.h>
#include <stdint.h>

#define LEVELS 9
#define N_NODES 87381          // (4^9-1)/3
#define N_INTERNAL 21845
#define LEAF_START 21845
#define LEAF_N 65536

// ---------------- scratch (device globals: allocation-free rule) ----------------
__device__ __half g_xH[(size_t)N_NODES * 256];         // fp16 x
__device__ __half g_hH[(size_t)N_NODES * 256];         // fp16 h
__device__ __half g_xioufq[(size_t)N_INTERNAL * 1280]; // internal [iou(768)|f(256)|q(256)] fp16
__device__ __half g_xiou_leaf[(size_t)LEAF_N * 768];   // leaf [iou] fp16
__device__ __half g_kv[(size_t)65536 * 512];           // fp16 k|v
__device__ __half g_aoutH[(size_t)16384 * 256];        // fp16 attention out
__device__ __half g_hu[(size_t)16384 * 1024];          // fp16 h_iou|h_f
// packed weights, transposed [N][256], fp16
__device__ __half g_Wcat2T[1280 * 256];                // [iou|f|q]
__device__ float  g_bcat2[1280];
__device__ __half g_WkvT[512 * 256];
__device__ float  g_bkv[512];
__device__ __half g_UcatT[1024 * 256];                 // [Uiou|Uf] transposed
__device__ __half g_WlR[256 * 256];                    // Wl row-major fp16
__device__ float  g_WcombRaw[256 * 1024];              // Wl@U fp32 [k][n]
__device__ __half g_WcombT[1024 * 256];                // transposed fp16
__device__ float  g_bcomb[1024];                       // bl@U + bU (fp32)
__device__ float  g_zero[1280];                        // stays zero

__device__ __forceinline__ float sigmoidf_(float x) { return 1.0f / (1.0f + expf(-x)); }

__device__ __forceinline__ void mma_fp16(float c[4],
                                         uint32_t a0, uint32_t a1, uint32_t a2, uint32_t a3,
                                         uint32_t b0, uint32_t b1) {
    asm volatile("mma.sync.aligned.m16n8k16.row.col.f32.f16.f16.f32 "
                 "{%0,%1,%2,%3}, {%4,%5,%6,%7}, {%8,%9}, {%0,%1,%2,%3};\n"
                 : "+f"(c[0]), "+f"(c[1]), "+f"(c[2]), "+f"(c[3])
                 : "r"(a0), "r"(a1), "r"(a2), "r"(a3), "r"(b0), "r"(b1));
}

__device__ __forceinline__ void ldsm_x4(uint32_t& r0, uint32_t& r1, uint32_t& r2, uint32_t& r3,
                                        uint32_t addr) {
    asm volatile("ldmatrix.sync.aligned.m8n8.x4.shared.b16 {%0,%1,%2,%3}, [%4];"
                 : "=r"(r0), "=r"(r1), "=r"(r2), "=r"(r3) : "r"(addr));
}

// ---------------- weight packing ----------------
__global__ void pack_weights(const float* __restrict__ W_iou, const float* __restrict__ b_iou,
                             const float* __restrict__ W_f,   const float* __restrict__ b_f,
                             const float* __restrict__ Wq,    const float* __restrict__ bq,
                             const float* __restrict__ Wk,    const float* __restrict__ bk,
                             const float* __restrict__ Wv,    const float* __restrict__ bv,
                             const float* __restrict__ Wl,
                             const float* __restrict__ Uiou_w,
                             const float* __restrict__ Uf_w)
{
    int idx = blockIdx.x * blockDim.x + threadIdx.x;
    if (idx >= 256 * 1280) return;
    int r = idx / 1280, c = idx % 1280;   // r = k row, c = output col
    float w2;
    if (c < 768)       w2 = W_iou[r * 768 + c];
    else if (c < 1024) w2 = W_f[r * 256 + (c - 768)];
    else               w2 = Wq[r * 256 + (c - 1024)];
    g_Wcat2T[c * 256 + r] = __float2half(w2);
    if (c < 1024) {
        float wu = (c < 768) ? Uiou_w[r * 768 + c] : Uf_w[r * 256 + (c - 768)];
        g_UcatT[c * 256 + r] = __float2half(wu);
    }
    if (c < 512) {
        float wk = (c < 256) ? Wk[r * 256 + c] : Wv[r * 256 + (c - 256)];
        g_WkvT[c * 256 + r] = __float2half(wk);
    }
    if (c < 256) g_WlR[r * 256 + c] = __float2half(Wl[r * 256 + c]);
    if (r == 0) {
        if (c < 768)       g_bcat2[c] = b_iou[c];
        else if (c < 1024) g_bcat2[c] = b_f[c - 768];
        else               g_bcat2[c] = bq[c - 1024];
        if (c < 512) g_bkv[c] = (c < 256) ? bk[c] : bv[c - 256];
    }
}

// transpose+convert Wcomb, and build bcomb = bl@U + bU (fp32 from originals)
__global__ void finish_comb(const float* __restrict__ bl,
                            const float* __restrict__ Uiou_w, const float* __restrict__ Uiou_b,
                            const float* __restrict__ Uf_w,   const float* __restrict__ Uf_b)
{
    int idx = blockIdx.x * blockDim.x + threadIdx.x;
    if (idx >= 256 * 1024) return;
    int k = idx >> 10, n = idx & 1023;
    g_WcombT[n * 256 + k] = __float2half(g_WcombRaw[k * 1024 + n]);
    if (k == 0) {
        float s = (n < 768) ? Uiou_b[n] : Uf_b[n - 768];
        for (int j = 0; j < 256; j++) {
            float u = (n < 768) ? Uiou_w[j * 768 + n] : Uf_w[j * 256 + (n - 768)];
            s += bl[j] * u;
        }
        g_bcomb[n] = s;
    }
}

// ---------------- x -> fp16 convert ----------------
__global__ void convert_x_kernel(const float* __restrict__ x)
{
    size_t i = (size_t)blockIdx.x * blockDim.x + threadIdx.x;
    if (i >= (size_t)N_NODES * 64) return;   // float4 count
    float4 v = reinterpret_cast<const float4*>(x)[i];
    __half2 h0 = __floats2half2_rn(v.x, v.y);
    __half2 h1 = __floats2half2_rn(v.z, v.w);
    uint2 pack;
    pack.x = *reinterpret_cast<uint32_t*>(&h0);
    pack.y = *reinterpret_cast<uint32_t*>(&h1);
    reinterpret_cast<uint2*>(g_xH)[i] = pack;
}

// ---------------- FP16 tensor-core GEMM, cp.async 3-stage pipeline ----------------
// C[M,N] = A[M,256] @ Bt[N,256]^T + bias[N].  N % 128 == 0.
#define STAGES 3
#define SROWH 40
#define STGH_BYTES (256 * SROWH * 2)      // 20480
#define GEMM_SMEM (STAGES * STGH_BYTES)   // 61440

__device__ __forceinline__ void issue_load(uint32_t sbase, int st,
                                           const __half* __restrict__ A,
                                           const __half* __restrict__ Bt,
                                           int row0, int col0, int M, int k0, int tid)
{
    uint32_t so = sbase + st * STGH_BYTES;
    int row4 = tid >> 2;
    int ch   = (tid & 3) * 8;
    #pragma unroll
    for (int i = 0; i < 4; i++) {
        int r = row4 + 32 * i;
        bool ok = (row0 + r) < M;
        uint32_t da = so + (r * SROWH + ch) * 2;
        const __half* ga = A + (size_t)(ok ? (row0 + r) : 0) * 256 + k0 + ch;
        int sz = ok ? 16 : 0;
        asm volatile("cp.async.cg.shared.global [%0], [%1], 16, %2;"
                     :: "r"(da), "l"(ga), "r"(sz) : "memory");
        uint32_t db = so + ((128 + r) * SROWH + ch) * 2;
        const __half* gb = Bt + (size_t)(col0 + r) * 256 + k0 + ch;
        asm volatile("cp.async.cg.shared.global [%0], [%1], 16;"
                     :: "r"(db), "l"(gb) : "memory");
    }
}

__device__ __forceinline__ void compute_stage(uint32_t soff,
                                              const uint32_t aoff[4], const uint32_t boff[4],
                                              float acc[4][8][4])
{
    #pragma unroll
    for (int kk = 0; kk < 32; kk += 16) {
        uint32_t af[4][4];
        #pragma unroll
        for (int mi = 0; mi < 4; mi++)
            ldsm_x4(af[mi][0], af[mi][1], af[mi][2], af[mi][3], soff + aoff[mi] + kk * 2);
        uint32_t bf[8][2];
        #pragma unroll
        for (int np = 0; np < 4; np++)
            ldsm_x4(bf[2 * np][0], bf[2 * np][1], bf[2 * np + 1][0], bf[2 * np + 1][1],
                    soff + boff[np] + kk * 2);
        #pragma unroll
        for (int mi = 0; mi < 4; mi++)
            #pragma unroll
            for (int ni = 0; ni < 8; ni++)
                mma_fp16(acc[mi][ni],
                         af[mi][0], af[mi][1], af[mi][2], af[mi][3],
                         bf[ni][0], bf[ni][1]);
    }
}

template <bool HALF_OUT>
__global__ void __launch_bounds__(128) gemm_fp16(const __half* __restrict__ A,
                                                 const __half* __restrict__ Bt,
                                                 const float* __restrict__ bias,
                                                 void* __restrict__ Cv, int M, int N)
{
    extern __shared__ uint32_t sm[];
    int tid  = threadIdx.x;
    int lane = tid & 31;
    int warp = tid >> 5;
    int wr = warp >> 1, wc = warp & 1;
    int g  = lane >> 3, r8 = lane & 7;
    int gid = lane >> 2, tig = lane & 3;
    int row0 = blockIdx.y * 128;
    int col0 = blockIdx.x * 128;

    uint32_t sbase = (uint32_t)__cvta_generic_to_shared(sm);
    uint32_t aoff[4], boff[4];
    #pragma unroll
    for (int mi = 0; mi < 4; mi++) {
        int row = wr * 64 + mi * 16 + ((g & 1) << 3) + r8;
        aoff[mi] = (row * SROWH + ((g >> 1) << 3)) * 2;
    }
    #pragma unroll
    for (int np = 0; np < 4; np++) {
        int row = 128 + wc * 64 + np * 16 + ((g >> 1) << 3) + r8;
        boff[np] = (row * SROWH + ((g & 1) << 3)) * 2;
    }

    float acc[4][8][4];
    #pragma unroll
    for (int mi = 0; mi < 4; mi++)
        #pragma unroll
        for (int ni = 0; ni < 8; ni++)
            #pragma unroll
            for (int t = 0; t < 4; t++) acc[mi][ni][t] = 0.0f;

    issue_load(sbase, 0, A, Bt, row0, col0, M, 0, tid);
    asm volatile("cp.async.commit_group;" ::: "memory");
    issue_load(sbase, 1, A, Bt, row0, col0, M, 32, tid);
    asm volatile("cp.async.commit_group;" ::: "memory");

    #pragma unroll
    for (int it = 0; it < 8; it++) {
        asm volatile("cp.async.wait_group 1;" ::: "memory");
        __syncthreads();
        compute_stage(sbase + (it % 3) * STGH_BYTES, aoff, boff, acc);
        if (it + 2 < 8)
            issue_load(sbase, (it + 2) % 3, A, Bt, row0, col0, M, (it + 2) * 32, tid);
        asm volatile("cp.async.commit_group;" ::: "memory");
    }

    float*  Cf = (float*)Cv;
    __half* Ch = (__half*)Cv;
    #pragma unroll
    for (int mi = 0; mi < 4; mi++) {
        int rbase = row0 + wr * 64 + mi * 16 + gid;
        #pragma unroll
        for (int ni = 0; ni < 8; ni++) {
            int c = col0 + wc * 64 + ni * 8 + 2 * tig;
            float b0 = bias[c], b1 = bias[c + 1];
            if (rbase < M) {
                float v0 = acc[mi][ni][0] + b0, v1 = acc[mi][ni][1] + b1;
                if (HALF_OUT)
                    *reinterpret_cast<__half2*>(Ch + (size_t)rbase * N + c) = __floats2half2_rn(v0, v1);
                else
                    *reinterpret_cast<float2*>(Cf + (size_t)rbase * N + c) = make_float2(v0, v1);
            }
            if (rbase + 8 < M) {
                float v2 = acc[mi][ni][2] + b0, v3 = acc[mi][ni][3] + b1;
                if (HALF_OUT)
                    *reinterpret_cast<__half2*>(Ch + (size_t)(rbase + 8) * N + c) = __floats2half2_rn(v2, v3);
                else
                    *reinterpret_cast<float2*>(Cf + (size_t)(rbase + 8) * N + c) = make_float2(v2, v3);
            }
        }
    }
}

__device__ __forceinline__ float4 load_h4(const __half* p) {
    // 4 consecutive halves -> float4 (p 8B aligned)
    uint2 raw = *reinterpret_cast<const uint2*>(p);
    __half2 a = *reinterpret_cast<__half2*>(&raw.x);
    __half2 b = *reinterpret_cast<__half2*>(&raw.y);
    float2 fa = __half22float2(a), fb = __half22float2(b);
    return make_float4(fa.x, fa.y, fb.x, fb.y);
}

// ---------------- leaf level: gates from g_xiou_leaf (half, stride 768) ----------------
__global__ void leaf_kernel(float* __restrict__ outH, float* __restrict__ outC)
{
    int t  = threadIdx.x;
    int jj = blockIdx.x * 4 + (t >> 6);
    int d  = (t & 63) * 4;
    const __half* r = g_xiou_leaf + (size_t)jj * 768;
    float4 iv = load_h4(r + d);
    float4 ov = load_h4(r + 256 + d);
    float4 uv = load_h4(r + 512 + d);
    float4 c4, h4;
    __half hh[4];
    #pragma unroll
    for (int q = 0; q < 4; q++) {
        float i = (&iv.x)[q], o = (&ov.x)[q], u = (&uv.x)[q];
        float c = sigmoidf_(i) * tanhf(u);
        float h = sigmoidf_(o) * tanhf(c);
        (&c4.x)[q] = c; (&h4.x)[q] = h; hh[q] = __float2half(h);
    }
    size_t base = (size_t)(LEAF_START + jj) * 256 + d;
    *reinterpret_cast<float4*>(outH + base) = h4;
    *reinterpret_cast<float4*>(outC + base) = c4;
    *reinterpret_cast<uint2*>(g_hH + base) = *reinterpret_cast<uint2*>(hh);
}

// ---------------- attention: warp per (node, head), all-fp16 reads ----------------
__global__ void attn_kernel(int s0)
{
    int j = blockIdx.x;
    int node = s0 + j;
    int w = threadIdx.x >> 5;
    int t = threadIdx.x & 31;
    const float scale = 0.17677669529663687f; // 1/sqrt(32)
    float qv = __half2float(g_xioufq[(size_t)node * 1280 + 1024 + w * 32 + t]);
    float logit[4];
    #pragma unroll
    for (int k = 0; k < 4; k++) {
        float kk = __half2float(g_kv[(size_t)(4 * j + k) * 512 + w * 32 + t]);
        float p = qv * kk;
        #pragma unroll
        for (int off = 16; off; off >>= 1) p += __shfl_xor_sync(0xffffffffu, p, off);
        logit[k] = p * scale;
    }
    float m = fmaxf(fmaxf(logit[0], logit[1]), fmaxf(logit[2], logit[3]));
    float e[4], s = 0.f;
    #pragma unroll
    for (int k = 0; k < 4; k++) { e[k] = expf(logit[k] - m); s += e[k]; }
    float inv = 1.0f / s;
    float o = 0.f;
    #pragma unroll
    for (int k = 0; k < 4; k++)
        o += e[k] * inv * __half2float(g_kv[(size_t)(4 * j + k) * 512 + 256 + w * 32 + t]);
    g_aoutH[(size_t)j * 256 + w * 32 + t] = __float2half(o);
}

// ---------------- internal-level gates ----------------
__global__ void gate_kernel(float* __restrict__ outH, float* __restrict__ outC,
                            int s0, int cs, int n)
{
    int t  = threadIdx.x;
    int jj = blockIdx.x * 4 + (t >> 6);
    if (jj >= n) return;
    int d  = (t & 63) * 4;
    int node = s0 + jj;
    const __half* xr = g_xioufq + (size_t)node * 1280;
    const __half* hr = g_hu + (size_t)jj * 1024;
    float4 i4 = load_h4(xr + d);
    float4 o4 = load_h4(xr + 256 + d);
    float4 u4 = load_h4(xr + 512 + d);
    float4 f4 = load_h4(xr + 768 + d);
    float4 hi = load_h4(hr + d);
    float4 ho = load_h4(hr + 256 + d);
    float4 hu4 = load_h4(hr + 512 + d);
    float4 hf = load_h4(hr + 768 + d);
    float4 cs4 = make_float4(0.f, 0.f, 0.f, 0.f);
    #pragma unroll
    for (int k = 0; k < 4; k++) {
        float4 cc = *reinterpret_cast<const float4*>(outC + (size_t)(cs + 4 * jj + k) * 256 + d);
        cs4.x += cc.x; cs4.y += cc.y; cs4.z += cc.z; cs4.w += cc.w;
    }
    float4 c4, h4;
    __half hh[4];
    #pragma unroll
    for (int q = 0; q < 4; q++) {
        float i = (&i4.x)[q] + (&hi.x)[q];
        float o = (&o4.x)[q] + (&ho.x)[q];
        float u = (&u4.x)[q] + (&hu4.x)[q];
        float f = sigmoidf_((&f4.x)[q] + (&hf.x)[q]);
        float c = sigmoidf_(i) * tanhf(u) + f * (&cs4.x)[q];
        float h = sigmoidf_(o) * tanhf(c);
        (&c4.x)[q] = c; (&h4.x)[q] = h; hh[q] = __float2half(h);
    }
    size_t base = (size_t)node * 256 + d;
    *reinterpret_cast<float4*>(outH + base) = h4;
    *reinterpret_cast<float4*>(outC + base) = c4;
    *reinterpret_cast<uint2*>(g_hH + base) = *reinterpret_cast<uint2*>(hh);
}

// ---------------- host launch ----------------
extern "C" void kernel_launch(void* const* d_in, const int* in_sizes, int n_in,
                              void* d_out, int out_size)
{
    const float* x      = (const float*)d_in[0];
    const float* W_iou  = (const float*)d_in[1];
    const float* b_iou  = (const float*)d_in[2];
    const float* W_f    = (const float*)d_in[3];
    const float* b_f    = (const float*)d_in[4];
    const float* Wq     = (const float*)d_in[5];
    const float* bq     = (const float*)d_in[6];
    const float* Wk     = (const float*)d_in[7];
    const float* bk     = (const float*)d_in[8];
    const float* Wv     = (const float*)d_in[9];
    const float* bv     = (const float*)d_in[10];
    const float* Wl     = (const float*)d_in[11];
    const float* bl     = (const float*)d_in[12];
    const float* Uiou_w = (const float*)d_in[13];
    const float* Uiou_b = (const float*)d_in[14];
    const float* Uf_w   = (const float*)d_in[15];
    const float* Uf_b   = (const float*)d_in[16];

    float* outH = (float*)d_out;
    float* outC = outH + (size_t)N_NODES * 256;

    static bool attr_set = false;
    if (!attr_set) {
        cudaFuncSetAttribute(gemm_fp16<false>, cudaFuncAttributeMaxDynamicSharedMemorySize, GEMM_SMEM);
        cudaFuncSetAttribute(gemm_fp16<true>,  cudaFuncAttributeMaxDynamicSharedMemorySize, GEMM_SMEM);
        attr_set = true;
    }

    __half *p_xH, *p_hH, *p_aoutH, *p_W2, *p_Wkv, *p_Uc, *p_WlR, *p_WcT;
    __half *p_xioufq, *p_xleaf, *p_kv, *p_hu;
    float *p_b2, *p_bkv, *p_WcR, *p_bc, *p_zero;
    cudaGetSymbolAddress((void**)&p_xH,     g_xH);
    cudaGetSymbolAddress((void**)&p_hH,     g_hH);
    cudaGetSymbolAddress((void**)&p_aoutH,  g_aoutH);
    cudaGetSymbolAddress((void**)&p_xioufq, g_xioufq);
    cudaGetSymbolAddress((void**)&p_xleaf,  g_xiou_leaf);
    cudaGetSymbolAddress((void**)&p_kv,     g_kv);
    cudaGetSymbolAddress((void**)&p_hu,     g_hu);
    cudaGetSymbolAddress((void**)&p_W2,     g_Wcat2T);
    cudaGetSymbolAddress((void**)&p_b2,     g_bcat2);
    cudaGetSymbolAddress((void**)&p_Wkv,    g_WkvT);
    cudaGetSymbolAddress((void**)&p_bkv,    g_bkv);
    cudaGetSymbolAddress((void**)&p_Uc,     g_UcatT);
    cudaGetSymbolAddress((void**)&p_WlR,    g_WlR);
    cudaGetSymbolAddress((void**)&p_WcR,    g_WcombRaw);
    cudaGetSymbolAddress((void**)&p_WcT,    g_WcombT);
    cudaGetSymbolAddress((void**)&p_bc,     g_bcomb);
    cudaGetSymbolAddress((void**)&p_zero,   g_zero);

    static const int starts[LEVELS + 1] =
        {0, 1, 5, 21, 85, 341, 1365, 5461, 21845, 87381};

    pack_weights<<<(256 * 1280 + 255) / 256, 256>>>(
        W_iou, b_iou, W_f, b_f, Wq, bq, Wk, bk, Wv, bv, Wl, Uiou_w, Uf_w);

    // Wcomb = WlR @ UcatT^T (256x1024) in fp32, then transpose+convert + bcomb
    {
        dim3 grid(1024 / 128, 2);
        gemm_fp16<false><<<grid, 128, GEMM_SMEM>>>(p_WlR, p_Uc, p_zero, p_WcR, 256, 1024);
    }
    finish_comb<<<(256 * 1024 + 255) / 256, 256>>>(bl, Uiou_w, Uiou_b, Uf_w, Uf_b);

    convert_x_kernel<<<(N_NODES * 64 + 255) / 256, 256>>>(x);

    // leaf iou (N=768, fp16 out) and internal iou|f|q (N=1280, fp16 out)
    {
        dim3 grid(768 / 128, LEAF_N / 128);
        gemm_fp16<true><<<grid, 128, GEMM_SMEM>>>(p_xH + (size_t)LEAF_START * 256,
                                                  p_W2, p_b2, p_xleaf, LEAF_N, 768);
    }
    leaf_kernel<<<LEAF_N / 4, 256>>>(outH, outC);
    {
        dim3 grid(1280 / 128, (N_INTERNAL + 127) / 128);
        gemm_fp16<true><<<grid, 128, GEMM_SMEM>>>(p_xH, p_W2, p_b2, p_xioufq, N_INTERNAL, 1280);
    }

    for (int l = LEVELS - 2; l >= 0; --l) {
        int n  = 1 << (2 * l);
        int s0 = starts[l];
        int cs = starts[l + 1];
        int nc = 4 * n;

        {
            dim3 grid(512 / 128, (nc + 127) / 128);
            gemm_fp16<true><<<grid, 128, GEMM_SMEM>>>(p_hH + (size_t)cs * 256,
                                                      p_Wkv, p_bkv, p_kv, nc, 512);
        }
        attn_kernel<<<n, 256>>>(s0);
        {
            dim3 grid(1024 / 128, (n + 127) / 128);
            gemm_fp16<true><<<grid, 128, GEMM_SMEM>>>(p_aoutH, p_WcT, p_bc, p_hu, n, 1024);
        }
        gate_kernel<<<(n + 3) / 4, 256>>>(outH, outC, s0, cs, n);
    }
}